// round 15
// baseline (speedup 1.0000x reference)
#include <cuda_runtime.h>
#include <cuda_fp16.h>
#include <cstddef>
#include <cstdint>

// Problem constants
#define Bn   256
#define Tn   512
#define Dn   64
#define Hn   512
#define G4H  2048   // 4*H
#define FCn  512
#define OUTn 8

#define GKC   16          // k-chunk in fp32 gemm kernel
#define MGRPS 8           // m-groups (Bn/32)
#define GRP_BLOCKS 16     // blocks per m-group (2048 cols / 128)

typedef unsigned long long ull;

#define SWZ128(off) ((off) ^ (((off) >> 3) & 0x70))

// ---------------- scratch (device globals; no runtime allocation) ----------
// xg in fp16, gate-interleaved layout: xg[m, t, u*4 + g]
__device__ __half g_xg[(size_t)Bn * Tn * G4H];
__device__ __half g_h0h[(size_t)Bn * Tn * Hn];     // layer-0 h, fp16 (feeds layer-1 GEMM)
__device__ float g_hfin[Bn * Hn];
__device__ float g_z[Bn * FCn];
// fp16 h state TRIPLE buffers (per-block-flag pipelining needs 3-deep WAR slack)
__device__ __half g_hb0[Bn * Hn], g_hb1[Bn * Hn], g_hb2[Bn * Hn];
// prepacked recurrent weights, fp16, [layer][u_tile(16)][chunk(8)][128n x 64k swizzled]
// n within tile = unit_local*4 + gate  (gate-interleaved)
__device__ __half g_Whh_hi[2][(size_t)G4H * Hn];
// fp16 pre-swizzled W_ih for mma gemm (gate-interleaved n)
__device__ uint4 g_Wb0hi[G4H * Dn / 8];            // layer0: 2048x64
__device__ uint4 g_Wb1hi[G4H * Hn / 8];            // layer1: 2048x512

// per-(group, block) producer flags, each in its own 128B line
__device__ unsigned g_hflag[MGRPS * GRP_BLOCKS * 32];

// ---------------- f32x2 packed helpers (fp32 FC1 gemm) ----------------------
__device__ __forceinline__ void ffma2(ull& d, ull a, ull b) {
    asm("fma.rn.f32x2 %0, %1, %2, %0;" : "+l"(d) : "l"(a), "l"(b));
}
__device__ __forceinline__ ull pack2dup(float x) {
    ull r; asm("mov.b64 %0, {%1, %1};" : "=l"(r) : "f"(x)); return r;
}
__device__ __forceinline__ float2 unpack2(ull v) {
    float2 f; asm("mov.b64 {%0, %1}, %2;" : "=f"(f.x), "=f"(f.y) : "l"(v)); return f;
}

// ---------------- fast activations (MUFU tanh) -------------------------------
__device__ __forceinline__ float tanha(float x) {
    float r; asm("tanh.approx.f32 %0, %1;" : "=f"(r) : "f"(x)); return r;
}
__device__ __forceinline__ float fsig(float x) {
    return fmaf(0.5f, tanha(0.5f * x), 0.5f);
}
__device__ __forceinline__ float ftanh(float x) { return tanha(x); }

// ---------------- cp.async helpers -----------------------------------------
__device__ __forceinline__ void cp_async16(void* smem_dst, const void* gmem_src) {
    unsigned saddr = (unsigned)__cvta_generic_to_shared(smem_dst);
    asm volatile("cp.async.cg.shared.global [%0], [%1], 16;" :: "r"(saddr), "l"(gmem_src));
}
__device__ __forceinline__ void cp_async16u(unsigned saddr, const void* gmem_src) {
    asm volatile("cp.async.cg.shared.global [%0], [%1], 16;" :: "r"(saddr), "l"(gmem_src));
}
__device__ __forceinline__ void cp_commit() { asm volatile("cp.async.commit_group;"); }
__device__ __forceinline__ void cp_wait0()  { asm volatile("cp.async.wait_group 0;" ::: "memory"); }
__device__ __forceinline__ void cp_wait1()  { asm volatile("cp.async.wait_group 1;" ::: "memory"); }

__device__ __forceinline__ unsigned smem_u32(const void* p) {
    return (unsigned)__cvta_generic_to_shared(p);
}
__device__ __forceinline__ uint32_t cvt_f16x2(float hi, float lo) {
    uint32_t r; asm("cvt.rn.f16x2.f32 %0, %1, %2;" : "=r"(r) : "f"(hi), "f"(lo)); return r;
}

// ---------------- release/acquire flag helpers ------------------------------
__device__ __forceinline__ unsigned ld_acq(const unsigned* p) {
    unsigned v;
    asm volatile("ld.acquire.gpu.global.u32 %0, [%1];" : "=r"(v) : "l"(p));
    return v;
}
__device__ __forceinline__ void red_rel_add(unsigned* p, unsigned v) {
    asm volatile("red.release.gpu.global.add.u32 [%0], %1;" :: "l"(p), "r"(v));
}

// ---------------- warp-level mma helpers ------------------------------------
__device__ __forceinline__ void ldsm_x4(uint32_t& r0, uint32_t& r1, uint32_t& r2, uint32_t& r3,
                                        uint32_t addr) {
    asm volatile("ldmatrix.sync.aligned.m8n8.x4.shared.b16 {%0,%1,%2,%3}, [%4];"
                 : "=r"(r0), "=r"(r1), "=r"(r2), "=r"(r3) : "r"(addr));
}
__device__ __forceinline__ void mma_f16(float* d, const uint32_t* a, const uint32_t* b) {
    asm volatile("mma.sync.aligned.m16n8k16.row.col.f32.f16.f16.f32 "
                 "{%0,%1,%2,%3}, {%4,%5,%6,%7}, {%8,%9}, {%0,%1,%2,%3};"
                 : "+f"(d[0]), "+f"(d[1]), "+f"(d[2]), "+f"(d[3])
                 : "r"(a[0]), "r"(a[1]), "r"(a[2]), "r"(a[3]), "r"(b[0]), "r"(b[1]));
}

// ---------------- legacy full group barrier (used once per layer, at end) ---
struct __align__(128) BarSlot { unsigned count; unsigned gen; unsigned pad[30]; };
__device__ BarSlot g_bar[MGRPS];

__device__ __forceinline__ void group_barrier(int grp) {
    __syncthreads();
    __threadfence();
    if (threadIdx.x == 0) {
        unsigned gen = atomicAdd(&g_bar[grp].gen, 0u);
        unsigned arrived = atomicAdd(&g_bar[grp].count, 1u);
        if (arrived == GRP_BLOCKS - 1u) {
            atomicExch(&g_bar[grp].count, 0u);
            __threadfence();
            atomicExch(&g_bar[grp].gen, gen + 1u);
        } else {
            while (atomicAdd(&g_bar[grp].gen, 0u) == gen) { __nanosleep(20); }
        }
    }
    __syncthreads();
}

// ---------------- weight pre-pack kernels -----------------------------------
// Whh [4H, H] -> per u-tile (32 units x 4 gates = 128 n-cols, n = un*4+gate)
// x 8 k-chunks, each chunk a 128n x 64k fp16 tile, SW128 swizzled.
__global__ void prepack_whh(const float* __restrict__ Whh,
                            __half* __restrict__ hi)
{
    int i = blockIdx.x * blockDim.x + threadIdx.x;   // 0 .. 2048*512-1
    int k = i & 511;
    int row = i >> 9;                                 // gate*512 + unit_global
    int gate = row >> 9;
    int ug = row & 511;
    int bu = ug >> 5, un = ug & 31;
    int n = un * 4 + gate;                            // gate-interleaved
    int c = k >> 6, lk = k & 63;
    size_t off = ((size_t)(bu * 8 + c)) * 8192 + (SWZ128(n * 128 + lk * 2) >> 1);
    hi[off] = __float2half(Whh[(size_t)row * Hn + k]);
}

// W (2048 x K) -> fp16, per (ntile, kchunk) 64x64 tile, SW128.
// n' = u*4 + gate (gate-interleaved output columns).
__global__ void prepack_b_kernel(const float* __restrict__ W,
                                 __half* __restrict__ hi,
                                 int K)
{
    int i = blockIdx.x * blockDim.x + threadIdx.x;
    int k = i % K;
    int n_orig = i / K;                               // gate*512 + u
    int np = (n_orig & 511) * 4 + (n_orig >> 9);
    int ntile = np >> 6, ln = np & 63;
    int kc = k >> 6, lk = k & 63;
    int nch = K >> 6;
    size_t off = ((size_t)(ntile * nch + kc)) * 4096 + (SWZ128(ln * 128 + lk * 2) >> 1);
    hi[off] = __float2half(W[(size_t)n_orig * K + k]);
}

// inverse column permutation: n' -> orig row index in bias arrays
__device__ __forceinline__ int borig(int np) { return (np & 3) * 512 + (np >> 2); }

// ---------------- HMMA fp16 GEMM: C(half) = A @ W^T + b1 (+b2) -------------
#define MMAG_SMEM (24576 + 1024)
__global__ void __launch_bounds__(256, 2)
mma_gemm_kernel(const void* __restrict__ Avoid,
                const uint4* __restrict__ Wbhi,
                const float* __restrict__ b1,
                const float* __restrict__ b2,
                __half* __restrict__ C,
                int K, int Ntot, int a_f16)
{
    extern __shared__ char dsm[];
    uint32_t usm = smem_u32(dsm);
    usm = (usm + 1023u) & ~1023u;
    const uint32_t uAhi = usm;              // 128 x 64 fp16 = 16KB
    const uint32_t uBhi = usm + 16384;      // 8KB

    const int bn = blockIdx.x;
    const int m0 = blockIdx.y * 128;
    const int n0 = bn * 64;
    const int tid = threadIdx.x;
    const int w = tid >> 5;
    const int lane = tid & 31;
    const int mw = (w & 3) * 32;
    const int nw = (w >> 2) * 32;
    const int nch = K >> 6;

    const uint32_t xorv  = (uint32_t)(lane & 7) << 4;
    const uint32_t aRow  = mw + (lane & 15);
    const uint32_t aKsel = (uint32_t)(lane >> 4) << 4;
    const uint32_t bRow  = nw + (lane & 7) + ((lane >> 4) << 3);
    const uint32_t bKsel = (uint32_t)((lane >> 3) & 1) << 4;

    float acc[2][4][4];
#pragma unroll
    for (int mt = 0; mt < 2; mt++)
#pragma unroll
        for (int nt = 0; nt < 4; nt++)
#pragma unroll
            for (int e = 0; e < 4; e++) acc[mt][nt][e] = 0.f;

    for (int c = 0; c < nch; c++) {
        if (c) __syncthreads();

        const uint4* sbh = Wbhi + ((size_t)bn * nch + c) * 512;
        cp_async16u(uBhi + (uint32_t)tid * 16,         sbh + tid);
        cp_async16u(uBhi + (uint32_t)(tid + 256) * 16, sbh + tid + 256);

        if (a_f16) {
            const uint4* Af = (const uint4*)Avoid;
            const int krow = K >> 3;
#pragma unroll
            for (int j = 0; j < 4; j++) {
                int idx = tid + j * 256;
                int r = idx >> 3, q = idx & 7;
                cp_async16u(uAhi + SWZ128((uint32_t)r * 128 + (uint32_t)q * 16),
                            Af + (size_t)(m0 + r) * krow + c * 8 + q);
            }
            cp_commit();
            cp_wait0();
            __syncthreads();
        } else {
            cp_commit();
            const float* A = (const float*)Avoid;
            const int k0 = c * 64;
#pragma unroll
            for (int it = 0; it < 8; it++) {
                int idx = tid + it * 256;
                int r = idx >> 4, f4 = idx & 15;
                float4 v = *(const float4*)(A + (size_t)(m0 + r) * K + k0 + f4 * 4);
                uint32_t h01 = cvt_f16x2(v.y, v.x);
                uint32_t h23 = cvt_f16x2(v.w, v.z);
                uint32_t sw = (uint32_t)r * 128 + (((uint32_t)f4 * 8) ^ (((uint32_t)r & 7) << 4));
                asm volatile("st.shared.v2.u32 [%0], {%1,%2};" :: "r"(uAhi + sw), "r"(h01), "r"(h23));
            }
            cp_wait0();
            __syncthreads();
        }

#pragma unroll
        for (int ks = 0; ks < 4; ks++) {
            const uint32_t kbA = ((uint32_t)(32 * ks) + aKsel) ^ xorv;
            const uint32_t kbB = ((uint32_t)(32 * ks) + bKsel) ^ xorv;
            uint32_t ah0[4], ah1[4];
            ldsm_x4(ah0[0], ah0[1], ah0[2], ah0[3], uAhi + aRow * 128 + kbA);
            ldsm_x4(ah1[0], ah1[1], ah1[2], ah1[3], uAhi + (aRow + 16) * 128 + kbA);
            uint32_t bh[8];
            ldsm_x4(bh[0], bh[1], bh[2], bh[3], uBhi + bRow * 128 + kbB);
            ldsm_x4(bh[4], bh[5], bh[6], bh[7], uBhi + (bRow + 16) * 128 + kbB);
#pragma unroll
            for (int mt = 0; mt < 2; mt++) {
                const uint32_t* Ah = mt ? ah1 : ah0;
#pragma unroll
                for (int nt = 0; nt < 4; nt++)
                    mma_f16(acc[mt][nt], Ah, bh + nt * 2);
            }
        }
    }

    const int gid = lane >> 2, tig = lane & 3;
    float2 bias[4];
#pragma unroll
    for (int nt = 0; nt < 4; nt++) {
        int col = n0 + nw + nt * 8 + tig * 2;
        int o0 = borig(col), o1 = borig(col + 1);
        bias[nt].x = b1[o0] + (b2 ? b2[o0] : 0.f);
        bias[nt].y = b1[o1] + (b2 ? b2[o1] : 0.f);
    }
#pragma unroll
    for (int mt = 0; mt < 2; mt++) {
        int row0 = m0 + mw + mt * 16 + gid;
#pragma unroll
        for (int nt = 0; nt < 4; nt++) {
            int col = n0 + nw + nt * 8 + tig * 2;
            uint32_t v0 = cvt_f16x2(acc[mt][nt][1] + bias[nt].y, acc[mt][nt][0] + bias[nt].x);
            uint32_t v1 = cvt_f16x2(acc[mt][nt][3] + bias[nt].y, acc[mt][nt][2] + bias[nt].x);
            *(uint32_t*)&C[(size_t)row0 * Ntot + col]       = v0;
            *(uint32_t*)&C[(size_t)(row0 + 8) * Ntot + col] = v1;
        }
    }
}

// ---------------- persistent HMMA fp16 LSTM layer kernel --------------------
// Grid (16, 8), 256 threads: block = 32 units x 4 gates (128 gate-interleaved
// n-cols) x 32 batch rows. W fp16 resident in smem (128KB). h fp16 staged per
// step (32KB).
// Sync: per-BLOCK flags (8 warp-releases per block per step). A consumer
// staging k-chunk c polls only the 2 producer blocks (2c, 2c+1) of that chunk,
// processing chunks cyclically starting from its own chunk (bu>>1). WAR safety
// across the pipelined skew comes from TRIPLE-buffered h.
#define STEP_SMEM (131072 + 32768 + 1024)
__global__ void __launch_bounds__(256)
lstm_layer_mma(const __half* __restrict__ xg,       // [B, T, 4H] gate-interleaved
               const uint4* __restrict__ Whi,       // prepacked, this layer
               __half* __restrict__ hb0, __half* __restrict__ hb1,
               __half* __restrict__ hb2,
               __half* __restrict__ h_all,          // layer0: [B,T,H] fp16; else null
               float* __restrict__ h_final)         // layer1: [B,H]; else null
{
    extern __shared__ char dsm[];
    uint32_t usm = smem_u32(dsm);
    usm = (usm + 1023u) & ~1023u;
    const uint32_t uWhi = usm;                      // 8 chunks x 16KB = 128KB
    const uint32_t uH   = usm + 131072;             // 8 chunks x 4KB = 32KB

    const int bu  = blockIdx.x;                     // u-tile 0..15
    const int grp = blockIdx.y;                     // m-group 0..7
    const int m0  = grp * 32;
    const int tid = threadIdx.x;
    const int w   = tid >> 5;
    const int lane = tid & 31;
    const int mw = (w & 1) * 16;                    // 16 rows per warp (of 32)
    const int nw = (w >> 1) * 32;                   // 32 cols per warp (of 128)

    const uint32_t xorv  = (uint32_t)(lane & 7) << 4;
    const uint32_t aRow  = mw + (lane & 15);
    const uint32_t aKsel = (uint32_t)(lane >> 4) << 4;
    const uint32_t bRow  = nw + (lane & 7) + ((lane >> 4) << 3);
    const uint32_t bKsel = (uint32_t)((lane >> 3) & 1) << 4;
    const int gid = lane >> 2, tig = lane & 3;
    const bool oddt = (tig & 1);
    const int cstart = bu >> 1;                     // this block's own k-chunk

    unsigned* flags  = &g_hflag[grp * GRP_BLOCKS * 32];
    unsigned* myflag = flags + bu * 32;

    // ---- load resident weights (once): 128KB = 8192 uint4 ----
    {
        const uint4* sh = Whi + (size_t)bu * 8192;
#pragma unroll
        for (int j = 0; j < 32; j++) {
            int idx = tid + j * 256;
            cp_async16u(uWhi + (uint32_t)idx * 16, sh + idx);
        }
        cp_commit();
        cp_wait0();
        __syncthreads();
    }

    // ---- per-thread cell mapping (from MMA fragment + shfl exchange) ----
    const int crow  = m0 + mw + gid + 8 * (tig & 1);
    const int ubase = bu * 32 + (w >> 1) * 8 + (tig >> 1);

    float creg[4] = {0.f, 0.f, 0.f, 0.f};
    float xvf[4][4];                                 // [nt][gate]
    {
        const __half* xr = xg + ((size_t)crow * Tn + 0) * G4H;
#pragma unroll
        for (int nt = 0; nt < 4; nt++) {
            uint2 p = __ldcg((const uint2*)(xr + (size_t)(ubase + nt * 2) * 4));
            float2 a = __half22float2(*(__half2*)&p.x);
            float2 b = __half22float2(*(__half2*)&p.y);
            xvf[nt][0] = a.x; xvf[nt][1] = a.y; xvf[nt][2] = b.x; xvf[nt][3] = b.y;
        }
    }

    // h staging per chunk: 32 rows x 64 k fp16 = 4KB = 256 cp.async = 1/thread
    const int s_r = tid >> 3, s_q = tid & 7;

    // triple-buffer rotation: prev (read h_{t-1}) / cur (write h_t) / nxt
    const __half* bprev = hb2;   // unused at t=0
    __half* bcur = hb0;
    __half* bnxt = hb1;

    for (int t = 0; t < Tn; t++) {
        const __half* hin = bprev;
        __half* hout      = bcur;

        float g4[4][4];                              // [nt][gate], recurrent part
#pragma unroll
        for (int nt = 0; nt < 4; nt++)
#pragma unroll
            for (int g = 0; g < 4; g++) g4[nt][g] = 0.f;

        if (t > 0) {
            const unsigned need = 8u * (unsigned)t;

            // issue commit group 0 (chunks cstart, cstart+1), polling its producers
#pragma unroll
            for (int g2 = 0; g2 < 1; g2++) { }
            {
                int cA = cstart, cB = (cstart + 1) & 7;
                if (lane < 4) {
                    int cc = (lane < 2) ? cA : cB;
                    while (ld_acq(flags + (cc * 2 + (lane & 1)) * 32) < need) { }
                }
                __syncwarp();
                cp_async16u(uH + (uint32_t)cA * 4096 +
                            SWZ128((uint32_t)s_r * 128 + (uint32_t)s_q * 16),
                            hin + (size_t)(m0 + s_r) * Hn + cA * 64 + s_q * 8);
                cp_async16u(uH + (uint32_t)cB * 4096 +
                            SWZ128((uint32_t)s_r * 128 + (uint32_t)s_q * 16),
                            hin + (size_t)(m0 + s_r) * Hn + cB * 64 + s_q * 8);
                cp_commit();
            }

            float acc[4][4];
#pragma unroll
            for (int nt = 0; nt < 4; nt++)
#pragma unroll
                for (int e = 0; e < 4; e++) acc[nt][e] = 0.f;

#pragma unroll
            for (int j = 0; j < 4; j++) {
                // issue group j+1 (prefetch) before waiting on group j
                if (j < 3) {
                    int cA = (cstart + 2 * j + 2) & 7, cB = (cstart + 2 * j + 3) & 7;
                    if (lane < 4) {
                        int cc = (lane < 2) ? cA : cB;
                        while (ld_acq(flags + (cc * 2 + (lane & 1)) * 32) < need) { }
                    }
                    __syncwarp();
                    cp_async16u(uH + (uint32_t)cA * 4096 +
                                SWZ128((uint32_t)s_r * 128 + (uint32_t)s_q * 16),
                                hin + (size_t)(m0 + s_r) * Hn + cA * 64 + s_q * 8);
                    cp_async16u(uH + (uint32_t)cB * 4096 +
                                SWZ128((uint32_t)s_r * 128 + (uint32_t)s_q * 16),
                                hin + (size_t)(m0 + s_r) * Hn + cB * 64 + s_q * 8);
                    cp_commit();
                    cp_wait1();
                } else {
                    cp_wait0();
                }
                __syncthreads();

#pragma unroll
                for (int ii = 0; ii < 2; ii++) {
                    const int c = (cstart + 2 * j + ii) & 7;
                    const uint32_t uA = uH + (uint32_t)c * 4096;
                    const uint32_t wh = uWhi + (uint32_t)c * 16384;
#pragma unroll
                    for (int ks = 0; ks < 4; ks++) {
                        const uint32_t kbA = ((uint32_t)(32 * ks) + aKsel) ^ xorv;
                        const uint32_t kbB = ((uint32_t)(32 * ks) + bKsel) ^ xorv;
                        uint32_t a0[4], bh[8];
                        ldsm_x4(a0[0], a0[1], a0[2], a0[3], uA + aRow * 128 + kbA);
                        ldsm_x4(bh[0], bh[1], bh[2], bh[3], wh + bRow * 128 + kbB);
                        ldsm_x4(bh[4], bh[5], bh[6], bh[7], wh + (bRow + 16) * 128 + kbB);
#pragma unroll
                        for (int nt = 0; nt < 4; nt++)
                            mma_f16(acc[nt], a0, bh + nt * 2);
                    }
                }
            }

            // gate exchange: pair (tig, tig^1) swaps so each thread gets all
            // 4 gates of one (row, unit) per nt.
#pragma unroll
            for (int nt = 0; nt < 4; nt++) {
                float s0 = __shfl_xor_sync(0xffffffffu, oddt ? acc[nt][0] : acc[nt][2], 1);
                float s1 = __shfl_xor_sync(0xffffffffu, oddt ? acc[nt][1] : acc[nt][3], 1);
                g4[nt][0] = oddt ? s0 : acc[nt][0];
                g4[nt][1] = oddt ? s1 : acc[nt][1];
                g4[nt][2] = oddt ? acc[nt][2] : s0;
                g4[nt][3] = oddt ? acc[nt][3] : s1;
            }
        }

        // ---- cell update: 4 cells per thread ----
        float hn4[4];
#pragma unroll
        for (int nt = 0; nt < 4; nt++) {
            float gi = g4[nt][0] + xvf[nt][0];
            float gf = g4[nt][1] + xvf[nt][1];
            float gg = g4[nt][2] + xvf[nt][2];
            float go = g4[nt][3] + xvf[nt][3];
            float cn = fsig(gf) * creg[nt] + fsig(gi) * ftanh(gg);
            creg[nt] = cn;
            hn4[nt] = fsig(go) * ftanh(cn);
        }

        // write h (fp16) then per-warp release of OWN flag ASAP
#pragma unroll
        for (int nt = 0; nt < 4; nt++)
            hout[(size_t)crow * Hn + (ubase + nt * 2)] = __float2half(hn4[nt]);
        if (t < Tn - 1) {
            __syncwarp();
            if (lane == 0) red_rel_add(myflag, 1u);
        }

        // off-critical-path: h_all / h_final, xg prefetch for t+1
        if (h_all) {
#pragma unroll
            for (int nt = 0; nt < 4; nt++)
                h_all[((size_t)crow * Tn + t) * Hn + (ubase + nt * 2)] = __float2half(hn4[nt]);
        }
        if (h_final && t == Tn - 1) {
#pragma unroll
            for (int nt = 0; nt < 4; nt++)
                h_final[(size_t)crow * Hn + (ubase + nt * 2)] = hn4[nt];
        }
        if (t < Tn - 1) {
            const __half* xr = xg + ((size_t)crow * Tn + (t + 1)) * G4H;
#pragma unroll
            for (int nt = 0; nt < 4; nt++) {
                uint2 p = __ldcg((const uint2*)(xr + (size_t)(ubase + nt * 2) * 4));
                float2 a = __half22float2(*(__half2*)&p.x);
                float2 b = __half22float2(*(__half2*)&p.y);
                xvf[nt][0] = a.x; xvf[nt][1] = a.y; xvf[nt][2] = b.x; xvf[nt][3] = b.y;
            }
        }

        // rotate triple buffer: prev <- cur, cur <- nxt, nxt <- old prev
        __half* oldprev = (__half*)bprev;
        bprev = bcur; bcur = bnxt; bnxt = oldprev;
    }

    // ---- end of layer: full barrier once, then reset flags (replay-safe) ----
    group_barrier(grp);
    if (bu == 0 && tid < GRP_BLOCKS) flags[tid * 32] = 0u;
}

// ---------------- fp32 tiled GEMM (kept for FC1) ----------------------------
__global__ void __launch_bounds__(256, 2)
gemm_bias_kernel(const float* __restrict__ A,
                 const float* __restrict__ W,
                 const float* __restrict__ b1,
                 const float* __restrict__ b2,
                 float* __restrict__ C,
                 int M, int N, int K, int relu)
{
    __shared__ __align__(16) float As[2][128][GKC];
    __shared__ __align__(16) float Bs[2][GKC][64];
    const int m0 = blockIdx.y * 128;
    const int n0 = blockIdx.x * 64;
    const int tid = threadIdx.x;
    const int cx = tid & 15;
    const int ry = tid >> 4;

    ull acc01[8], acc23[8];
#pragma unroll
    for (int i = 0; i < 8; i++) { acc01[i] = 0ull; acc23[i] = 0ull; }

    const int nch = K / GKC;
    const int bcol = tid & 63, bq = tid >> 6;

#pragma unroll
    for (int i = 0; i < 2; i++) {
        int idx = tid + i * 256;
        cp_async16(&As[0][idx >> 2][(idx & 3) * 4],
                   A + (size_t)(m0 + (idx >> 2)) * K + (idx & 3) * 4);
    }
    cp_commit();
    float4 pW = *(const float4*)(W + (size_t)(n0 + bcol) * K + bq * 4);
    Bs[0][bq * 4 + 0][bcol] = pW.x;
    Bs[0][bq * 4 + 1][bcol] = pW.y;
    Bs[0][bq * 4 + 2][bcol] = pW.z;
    Bs[0][bq * 4 + 3][bcol] = pW.w;

    for (int c = 0; c < nch; c++) {
        cp_wait0();
        __syncthreads();
        const int buf = c & 1;
        const bool more = (c + 1 < nch);
        if (more) {
            int k0 = (c + 1) * GKC;
#pragma unroll
            for (int i = 0; i < 2; i++) {
                int idx = tid + i * 256;
                cp_async16(&As[buf ^ 1][idx >> 2][(idx & 3) * 4],
                           A + (size_t)(m0 + (idx >> 2)) * K + k0 + (idx & 3) * 4);
            }
            cp_commit();
            pW = *(const float4*)(W + (size_t)(n0 + bcol) * K + k0 + bq * 4);
        }
#pragma unroll
        for (int k4 = 0; k4 < GKC; k4 += 4) {
            float4 a4[8];
#pragma unroll
            for (int i = 0; i < 8; i++) a4[i] = *(const float4*)&As[buf][ry + 16 * i][k4];
#pragma unroll
            for (int j = 0; j < 4; j++) {
                float4 w4 = *(const float4*)&Bs[buf][k4 + j][4 * cx];
                ull w01 = *reinterpret_cast<ull*>(&w4.x);
                ull w23 = *reinterpret_cast<ull*>(&w4.z);
#pragma unroll
                for (int i = 0; i < 8; i++) {
                    float av = (j == 0) ? a4[i].x : (j == 1) ? a4[i].y : (j == 2) ? a4[i].z : a4[i].w;
                    ull ad = pack2dup(av);
                    ffma2(acc01[i], ad, w01);
                    ffma2(acc23[i], ad, w23);
                }
            }
        }
        if (more) {
            Bs[buf ^ 1][bq * 4 + 0][bcol] = pW.x;
            Bs[buf ^ 1][bq * 4 + 1][bcol] = pW.y;
            Bs[buf ^ 1][bq * 4 + 2][bcol] = pW.z;
            Bs[buf ^ 1][bq * 4 + 3][bcol] = pW.w;
        }
    }

    const int col = n0 + 4 * cx;
    float bb0 = b1[col + 0], bb1 = b1[col + 1], bb2 = b1[col + 2], bb3 = b1[col + 3];
    if (b2) { bb0 += b2[col + 0]; bb1 += b2[col + 1]; bb2 += b2[col + 2]; bb3 += b2[col + 3]; }
#pragma unroll
    for (int i = 0; i < 8; i++) {
        int row = m0 + ry + 16 * i;
        float2 p01 = unpack2(acc01[i]);
        float2 p23 = unpack2(acc23[i]);
        float4 v;
        v.x = p01.x + bb0; v.y = p01.y + bb1; v.z = p23.x + bb2; v.w = p23.y + bb3;
        if (relu) { v.x = fmaxf(v.x, 0.f); v.y = fmaxf(v.y, 0.f); v.z = fmaxf(v.z, 0.f); v.w = fmaxf(v.w, 0.f); }
        *(float4*)&C[(size_t)row * N + col] = v;
    }
}

// ---------------- FC2: out[256,8] = z @ W_fc2^T + b ------------------------
__global__ void fc2_kernel(const float* __restrict__ z,
                           const float* __restrict__ W,
                           const float* __restrict__ b,
                           float* __restrict__ out)
{
    int row = blockIdx.x;
    int o = threadIdx.y;
    int lane = threadIdx.x;
    float s = 0.f;
    const float* zr = z + (size_t)row * FCn;
    const float* wr = W + (size_t)o * FCn;
    for (int k = lane; k < FCn; k += 32) s += zr[k] * wr[k];
#pragma unroll
    for (int off = 16; off; off >>= 1) s += __shfl_down_sync(0xffffffffu, s, off);
    if (lane == 0) out[row * OUTn + o] = s + b[o];
}

// ---------------- host orchestration ---------------------------------------
extern "C" void kernel_launch(void* const* d_in, const int* in_sizes, int n_in,
                              void* d_out, int out_size)
{
    const float* x      = (const float*)d_in[0];
    const float* W_ih0  = (const float*)d_in[1];
    const float* W_hh0  = (const float*)d_in[2];
    const float* b_ih0  = (const float*)d_in[3];
    const float* b_hh0  = (const float*)d_in[4];
    const float* W_ih1  = (const float*)d_in[5];
    const float* W_hh1  = (const float*)d_in[6];
    const float* b_ih1  = (const float*)d_in[7];
    const float* b_hh1  = (const float*)d_in[8];
    const float* W_fc1  = (const float*)d_in[9];
    const float* b_fc1  = (const float*)d_in[10];
    const float* W_fc2  = (const float*)d_in[11];
    const float* b_fc2  = (const float*)d_in[12];
    float* out = (float*)d_out;

    float *hfin, *z;
    __half *xg, *h0h, *hb0, *hb1, *hb2, *whhHi;
    uint4 *wb0h, *wb1h;
    cudaGetSymbolAddress((void**)&xg,    g_xg);
    cudaGetSymbolAddress((void**)&h0h,   g_h0h);
    cudaGetSymbolAddress((void**)&hfin,  g_hfin);
    cudaGetSymbolAddress((void**)&z,     g_z);
    cudaGetSymbolAddress((void**)&hb0,   g_hb0);
    cudaGetSymbolAddress((void**)&hb1,   g_hb1);
    cudaGetSymbolAddress((void**)&hb2,   g_hb2);
    cudaGetSymbolAddress((void**)&whhHi, g_Whh_hi);
    cudaGetSymbolAddress((void**)&wb0h,  g_Wb0hi);
    cudaGetSymbolAddress((void**)&wb1h,  g_Wb1hi);

    cudaFuncSetAttribute(mma_gemm_kernel, cudaFuncAttributeMaxDynamicSharedMemorySize, MMAG_SMEM);
    cudaFuncSetAttribute(lstm_layer_mma,  cudaFuncAttributeMaxDynamicSharedMemorySize, STEP_SMEM);

    const int MT = Bn * Tn;                 // 131072
    dim3 mmaGrid(G4H / 64, MT / 128);       // (32, 1024)
    dim3 stepGrid(16, MGRPS);               // (16, 8) = 128 blocks

    const size_t WHL = (size_t)G4H * Hn;    // per-layer whh elements
    prepack_whh<<<(G4H * Hn) / 256, 256>>>(W_hh0, whhHi);
    prepack_whh<<<(G4H * Hn) / 256, 256>>>(W_hh1, whhHi + WHL);
    prepack_b_kernel<<<(G4H * Dn) / 256, 256>>>(W_ih0, (__half*)wb0h, Dn);
    prepack_b_kernel<<<(G4H * Hn) / 256, 256>>>(W_ih1, (__half*)wb1h, Hn);

    // ---- Layer 0 ----  xg = x @ W_ih0^T + b_ih0 + b_hh0 (K=64, A fp32)
    mma_gemm_kernel<<<mmaGrid, 256, MMAG_SMEM>>>(x, wb0h, b_ih0, b_hh0, xg, Dn, G4H, 0);
    lstm_layer_mma<<<stepGrid, 256, STEP_SMEM>>>(xg, (const uint4*)whhHi,
                                                 hb0, hb1, hb2, h0h, (float*)0);

    // ---- Layer 1 ----  xg = h0 @ W_ih1^T + b_ih1 + b_hh1 (K=512, A fp16)
    mma_gemm_kernel<<<mmaGrid, 256, MMAG_SMEM>>>(h0h, wb1h, b_ih1, b_hh1, xg, Hn, G4H, 1);
    lstm_layer_mma<<<stepGrid, 256, STEP_SMEM>>>(xg, (const uint4*)(whhHi + WHL),
                                                 hb0, hb1, hb2, (__half*)0, hfin);

    // ---- FC head ----
    dim3 fc1Grid(FCn / 64, Bn / 128);       // (8, 2)
    gemm_bias_kernel<<<fc1Grid, 256>>>(hfin, W_fc1, b_fc1, (const float*)0, z, Bn, FCn, Hn, 1);
    fc2_kernel<<<Bn, dim3(32, 8)>>>(z, W_fc2, b_fc2, out);
}

// round 16
// speedup vs baseline: 1.1094x; 1.1094x over previous
#include <cuda_runtime.h>
#include <cuda_fp16.h>
#include <cstddef>
#include <cstdint>

// Problem constants
#define Bn   256
#define Tn   512
#define Dn   64
#define Hn   512
#define G4H  2048   // 4*H
#define FCn  512
#define OUTn 8

#define GKC   16          // k-chunk in fp32 gemm kernel
#define MGRPS 8           // m-groups (Bn/32)
#define GRP_BLOCKS 16     // blocks per m-group (2048 cols / 128)

typedef unsigned long long ull;

#define SWZ128(off) ((off) ^ (((off) >> 3) & 0x70))

// ---------------- scratch (device globals; no runtime allocation) ----------
// xg in fp16, gate-interleaved layout: xg[m, t, u*4 + g]
__device__ __half g_xg[(size_t)Bn * Tn * G4H];
__device__ __half g_h0h[(size_t)Bn * Tn * Hn];     // layer-0 h, fp16 (feeds layer-1 GEMM)
__device__ float g_hfin[Bn * Hn];
__device__ float g_z[Bn * FCn];
// fp16 h state double buffers
__device__ __half g_hX[Bn * Hn], g_hY[Bn * Hn];
// prepacked recurrent weights, fp16, [layer][u_tile(16)][chunk(8)][128n x 64k swizzled]
// n within tile = unit_local*4 + gate  (gate-interleaved)
__device__ __half g_Whh_hi[2][(size_t)G4H * Hn];
// fp16 pre-swizzled W_ih for mma gemm (gate-interleaved n)
__device__ uint4 g_Wb0hi[G4H * Dn / 8];            // layer0: 2048x64
__device__ uint4 g_Wb1hi[G4H * Hn / 8];            // layer1: 2048x512

// producer-progress flags (one per m-group, padded to 128B)
__device__ unsigned g_hflag[MGRPS * 32];

// ---------------- f32x2 packed helpers (fp32 FC1 gemm) ----------------------
__device__ __forceinline__ void ffma2(ull& d, ull a, ull b) {
    asm("fma.rn.f32x2 %0, %1, %2, %0;" : "+l"(d) : "l"(a), "l"(b));
}
__device__ __forceinline__ ull pack2dup(float x) {
    ull r; asm("mov.b64 %0, {%1, %1};" : "=l"(r) : "f"(x)); return r;
}
__device__ __forceinline__ float2 unpack2(ull v) {
    float2 f; asm("mov.b64 {%0, %1}, %2;" : "=f"(f.x), "=f"(f.y) : "l"(v)); return f;
}

// ---------------- fast activations (MUFU tanh; validated rel_err-neutral) ---
__device__ __forceinline__ float tanha(float x) {
    float r; asm("tanh.approx.f32 %0, %1;" : "=f"(r) : "f"(x)); return r;
}
__device__ __forceinline__ float fsig(float x) {
    return fmaf(0.5f, tanha(0.5f * x), 0.5f);
}
__device__ __forceinline__ float ftanh(float x) { return tanha(x); }

// ---------------- cp.async helpers -----------------------------------------
__device__ __forceinline__ void cp_async16(void* smem_dst, const void* gmem_src) {
    unsigned saddr = (unsigned)__cvta_generic_to_shared(smem_dst);
    asm volatile("cp.async.cg.shared.global [%0], [%1], 16;" :: "r"(saddr), "l"(gmem_src));
}
__device__ __forceinline__ void cp_async16u(unsigned saddr, const void* gmem_src) {
    asm volatile("cp.async.cg.shared.global [%0], [%1], 16;" :: "r"(saddr), "l"(gmem_src));
}
__device__ __forceinline__ void cp_commit() { asm volatile("cp.async.commit_group;"); }
__device__ __forceinline__ void cp_wait0()  { asm volatile("cp.async.wait_group 0;" ::: "memory"); }
__device__ __forceinline__ void cp_wait1()  { asm volatile("cp.async.wait_group 1;" ::: "memory"); }
__device__ __forceinline__ void cp_wait2()  { asm volatile("cp.async.wait_group 2;" ::: "memory"); }
__device__ __forceinline__ void cp_wait3()  { asm volatile("cp.async.wait_group 3;" ::: "memory"); }

__device__ __forceinline__ unsigned smem_u32(const void* p) {
    return (unsigned)__cvta_generic_to_shared(p);
}
__device__ __forceinline__ uint32_t cvt_f16x2(float hi, float lo) {
    uint32_t r; asm("cvt.rn.f16x2.f32 %0, %1, %2;" : "=r"(r) : "f"(hi), "f"(lo)); return r;
}

// ---------------- release/acquire flag helpers ------------------------------
__device__ __forceinline__ unsigned ld_acq(const unsigned* p) {
    unsigned v;
    asm volatile("ld.acquire.gpu.global.u32 %0, [%1];" : "=r"(v) : "l"(p));
    return v;
}
__device__ __forceinline__ void red_rel_add(unsigned* p, unsigned v) {
    asm volatile("red.release.gpu.global.add.u32 [%0], %1;" :: "l"(p), "r"(v));
}

// ---------------- warp-level mma helpers ------------------------------------
__device__ __forceinline__ void ldsm_x4(uint32_t& r0, uint32_t& r1, uint32_t& r2, uint32_t& r3,
                                        uint32_t addr) {
    asm volatile("ldmatrix.sync.aligned.m8n8.x4.shared.b16 {%0,%1,%2,%3}, [%4];"
                 : "=r"(r0), "=r"(r1), "=r"(r2), "=r"(r3) : "r"(addr));
}
__device__ __forceinline__ void mma_f16(float* d, const uint32_t* a, const uint32_t* b) {
    asm volatile("mma.sync.aligned.m16n8k16.row.col.f32.f16.f16.f32 "
                 "{%0,%1,%2,%3}, {%4,%5,%6,%7}, {%8,%9}, {%0,%1,%2,%3};"
                 : "+f"(d[0]), "+f"(d[1]), "+f"(d[2]), "+f"(d[3])
                 : "r"(a[0]), "r"(a[1]), "r"(a[2]), "r"(a[3]), "r"(b[0]), "r"(b[1]));
}

// ---------------- legacy full group barrier (used once per layer, at end) ---
struct __align__(128) BarSlot { unsigned count; unsigned gen; unsigned pad[30]; };
__device__ BarSlot g_bar[MGRPS];

__device__ __forceinline__ void group_barrier(int grp) {
    __syncthreads();
    __threadfence();
    if (threadIdx.x == 0) {
        unsigned gen = atomicAdd(&g_bar[grp].gen, 0u);
        unsigned arrived = atomicAdd(&g_bar[grp].count, 1u);
        if (arrived == GRP_BLOCKS - 1u) {
            atomicExch(&g_bar[grp].count, 0u);
            __threadfence();
            atomicExch(&g_bar[grp].gen, gen + 1u);
        } else {
            while (atomicAdd(&g_bar[grp].gen, 0u) == gen) { __nanosleep(20); }
        }
    }
    __syncthreads();
}

// ---------------- weight pre-pack kernels -----------------------------------
// Whh [4H, H] -> per u-tile (32 units x 4 gates = 128 n-cols, n = un*4+gate)
// x 8 k-chunks, each chunk a 128n x 64k fp16 tile, SW128 swizzled.
__global__ void prepack_whh(const float* __restrict__ Whh,
                            __half* __restrict__ hi)
{
    int i = blockIdx.x * blockDim.x + threadIdx.x;   // 0 .. 2048*512-1
    int k = i & 511;
    int row = i >> 9;                                 // gate*512 + unit_global
    int gate = row >> 9;
    int ug = row & 511;
    int bu = ug >> 5, un = ug & 31;
    int n = un * 4 + gate;                            // gate-interleaved
    int c = k >> 6, lk = k & 63;
    size_t off = ((size_t)(bu * 8 + c)) * 8192 + (SWZ128(n * 128 + lk * 2) >> 1);
    hi[off] = __float2half(Whh[(size_t)row * Hn + k]);
}

// W (2048 x K) -> fp16, per (ntile, kchunk) 64x64 tile, SW128.
// n' = u*4 + gate (gate-interleaved output columns).
__global__ void prepack_b_kernel(const float* __restrict__ W,
                                 __half* __restrict__ hi,
                                 int K)
{
    int i = blockIdx.x * blockDim.x + threadIdx.x;
    int k = i % K;
    int n_orig = i / K;                               // gate*512 + u
    int np = (n_orig & 511) * 4 + (n_orig >> 9);
    int ntile = np >> 6, ln = np & 63;
    int kc = k >> 6, lk = k & 63;
    int nch = K >> 6;
    size_t off = ((size_t)(ntile * nch + kc)) * 4096 + (SWZ128(ln * 128 + lk * 2) >> 1);
    hi[off] = __float2half(W[(size_t)n_orig * K + k]);
}

// inverse column permutation: n' -> orig row index in bias arrays
__device__ __forceinline__ int borig(int np) { return (np & 3) * 512 + (np >> 2); }

// ---------------- HMMA fp16 GEMM: C(half) = A @ W^T + b1 (+b2) -------------
#define MMAG_SMEM (24576 + 1024)
__global__ void __launch_bounds__(256, 2)
mma_gemm_kernel(const void* __restrict__ Avoid,
                const uint4* __restrict__ Wbhi,
                const float* __restrict__ b1,
                const float* __restrict__ b2,
                __half* __restrict__ C,
                int K, int Ntot, int a_f16)
{
    extern __shared__ char dsm[];
    uint32_t usm = smem_u32(dsm);
    usm = (usm + 1023u) & ~1023u;
    const uint32_t uAhi = usm;              // 128 x 64 fp16 = 16KB
    const uint32_t uBhi = usm + 16384;      // 8KB

    const int bn = blockIdx.x;
    const int m0 = blockIdx.y * 128;
    const int n0 = bn * 64;
    const int tid = threadIdx.x;
    const int w = tid >> 5;
    const int lane = tid & 31;
    const int mw = (w & 3) * 32;
    const int nw = (w >> 2) * 32;
    const int nch = K >> 6;

    const uint32_t xorv  = (uint32_t)(lane & 7) << 4;
    const uint32_t aRow  = mw + (lane & 15);
    const uint32_t aKsel = (uint32_t)(lane >> 4) << 4;
    const uint32_t bRow  = nw + (lane & 7) + ((lane >> 4) << 3);
    const uint32_t bKsel = (uint32_t)((lane >> 3) & 1) << 4;

    float acc[2][4][4];
#pragma unroll
    for (int mt = 0; mt < 2; mt++)
#pragma unroll
        for (int nt = 0; nt < 4; nt++)
#pragma unroll
            for (int e = 0; e < 4; e++) acc[mt][nt][e] = 0.f;

    for (int c = 0; c < nch; c++) {
        if (c) __syncthreads();

        const uint4* sbh = Wbhi + ((size_t)bn * nch + c) * 512;
        cp_async16u(uBhi + (uint32_t)tid * 16,         sbh + tid);
        cp_async16u(uBhi + (uint32_t)(tid + 256) * 16, sbh + tid + 256);

        if (a_f16) {
            const uint4* Af = (const uint4*)Avoid;
            const int krow = K >> 3;
#pragma unroll
            for (int j = 0; j < 4; j++) {
                int idx = tid + j * 256;
                int r = idx >> 3, q = idx & 7;
                cp_async16u(uAhi + SWZ128((uint32_t)r * 128 + (uint32_t)q * 16),
                            Af + (size_t)(m0 + r) * krow + c * 8 + q);
            }
            cp_commit();
            cp_wait0();
            __syncthreads();
        } else {
            cp_commit();
            const float* A = (const float*)Avoid;
            const int k0 = c * 64;
#pragma unroll
            for (int it = 0; it < 8; it++) {
                int idx = tid + it * 256;
                int r = idx >> 4, f4 = idx & 15;
                float4 v = *(const float4*)(A + (size_t)(m0 + r) * K + k0 + f4 * 4);
                uint32_t h01 = cvt_f16x2(v.y, v.x);
                uint32_t h23 = cvt_f16x2(v.w, v.z);
                uint32_t sw = (uint32_t)r * 128 + (((uint32_t)f4 * 8) ^ (((uint32_t)r & 7) << 4));
                asm volatile("st.shared.v2.u32 [%0], {%1,%2};" :: "r"(uAhi + sw), "r"(h01), "r"(h23));
            }
            cp_wait0();
            __syncthreads();
        }

#pragma unroll
        for (int ks = 0; ks < 4; ks++) {
            const uint32_t kbA = ((uint32_t)(32 * ks) + aKsel) ^ xorv;
            const uint32_t kbB = ((uint32_t)(32 * ks) + bKsel) ^ xorv;
            uint32_t ah0[4], ah1[4];
            ldsm_x4(ah0[0], ah0[1], ah0[2], ah0[3], uAhi + aRow * 128 + kbA);
            ldsm_x4(ah1[0], ah1[1], ah1[2], ah1[3], uAhi + (aRow + 16) * 128 + kbA);
            uint32_t bh[8];
            ldsm_x4(bh[0], bh[1], bh[2], bh[3], uBhi + bRow * 128 + kbB);
            ldsm_x4(bh[4], bh[5], bh[6], bh[7], uBhi + (bRow + 16) * 128 + kbB);
#pragma unroll
            for (int mt = 0; mt < 2; mt++) {
                const uint32_t* Ah = mt ? ah1 : ah0;
#pragma unroll
                for (int nt = 0; nt < 4; nt++)
                    mma_f16(acc[mt][nt], Ah, bh + nt * 2);
            }
        }
    }

    const int gid = lane >> 2, tig = lane & 3;
    float2 bias[4];
#pragma unroll
    for (int nt = 0; nt < 4; nt++) {
        int col = n0 + nw + nt * 8 + tig * 2;
        int o0 = borig(col), o1 = borig(col + 1);
        bias[nt].x = b1[o0] + (b2 ? b2[o0] : 0.f);
        bias[nt].y = b1[o1] + (b2 ? b2[o1] : 0.f);
    }
#pragma unroll
    for (int mt = 0; mt < 2; mt++) {
        int row0 = m0 + mw + mt * 16 + gid;
#pragma unroll
        for (int nt = 0; nt < 4; nt++) {
            int col = n0 + nw + nt * 8 + tig * 2;
            uint32_t v0 = cvt_f16x2(acc[mt][nt][1] + bias[nt].y, acc[mt][nt][0] + bias[nt].x);
            uint32_t v1 = cvt_f16x2(acc[mt][nt][3] + bias[nt].y, acc[mt][nt][2] + bias[nt].x);
            *(uint32_t*)&C[(size_t)row0 * Ntot + col]       = v0;
            *(uint32_t*)&C[(size_t)(row0 + 8) * Ntot + col] = v1;
        }
    }
}

// ---------------- persistent HMMA fp16 LSTM layer kernel --------------------
// Grid (16, 8), 256 threads: block = 32 units x 4 gates (128 gate-interleaved
// n-cols) x 32 batch rows. W fp16 resident in smem (128KB). h fp16 staged per
// step (32KB, 4 commit groups of 2 chunks — first MMA starts after only 8KB).
// Sync: single per-group release flag; per-warp acquire poll.
// Epilogue: gate exchange via one shfl.xor(1) pair; MUFU tanh activations.
#define STEP_SMEM (131072 + 32768 + 1024)
__global__ void __launch_bounds__(256)
lstm_layer_mma(const __half* __restrict__ xg,       // [B, T, 4H] gate-interleaved
               const uint4* __restrict__ Whi,       // prepacked, this layer
               __half* __restrict__ hX, __half* __restrict__ hY,
               __half* __restrict__ h_all,          // layer0: [B,T,H] fp16; else null
               float* __restrict__ h_final)         // layer1: [B,H]; else null
{
    extern __shared__ char dsm[];
    uint32_t usm = smem_u32(dsm);
    usm = (usm + 1023u) & ~1023u;
    const uint32_t uWhi = usm;                      // 8 chunks x 16KB = 128KB
    const uint32_t uH   = usm + 131072;             // 8 chunks x 4KB = 32KB

    const int bu  = blockIdx.x;                     // u-tile 0..15
    const int grp = blockIdx.y;                     // m-group 0..7
    const int m0  = grp * 32;
    const int tid = threadIdx.x;
    const int w   = tid >> 5;
    const int lane = tid & 31;
    const int mw = (w & 1) * 16;                    // 16 rows per warp (of 32)
    const int nw = (w >> 1) * 32;                   // 32 cols per warp (of 128)

    const uint32_t xorv  = (uint32_t)(lane & 7) << 4;
    const uint32_t aRow  = mw + (lane & 15);
    const uint32_t aKsel = (uint32_t)(lane >> 4) << 4;
    const uint32_t bRow  = nw + (lane & 7) + ((lane >> 4) << 3);
    const uint32_t bKsel = (uint32_t)((lane >> 3) & 1) << 4;
    const int gid = lane >> 2, tig = lane & 3;
    const bool oddt = (tig & 1);

    unsigned* flag = &g_hflag[grp * 32];

    // ---- load resident weights (once): 128KB = 8192 uint4 ----
    {
        const uint4* sh = Whi + (size_t)bu * 8192;
#pragma unroll
        for (int j = 0; j < 32; j++) {
            int idx = tid + j * 256;
            cp_async16u(uWhi + (uint32_t)idx * 16, sh + idx);
        }
        cp_commit();
        cp_wait0();
        __syncthreads();
    }

    // ---- per-thread cell mapping (from MMA fragment + shfl exchange) ----
    const int crow  = m0 + mw + gid + 8 * (tig & 1);
    const int ubase = bu * 32 + (w >> 1) * 8 + (tig >> 1);

    float creg[4] = {0.f, 0.f, 0.f, 0.f};
    float xvf[4][4];                                 // [nt][gate]
    {
        const __half* xr = xg + ((size_t)crow * Tn + 0) * G4H;
#pragma unroll
        for (int nt = 0; nt < 4; nt++) {
            uint2 p = __ldcg((const uint2*)(xr + (size_t)(ubase + nt * 2) * 4));
            float2 a = __half22float2(*(__half2*)&p.x);
            float2 b = __half22float2(*(__half2*)&p.y);
            xvf[nt][0] = a.x; xvf[nt][1] = a.y; xvf[nt][2] = b.x; xvf[nt][3] = b.y;
        }
    }

    // h staging per chunk: 32 rows x 64 k fp16 = 4KB = 256 cp.async = 1/thread
    const int s_r = tid >> 3, s_q = tid & 7;

    for (int t = 0; t < Tn; t++) {
        const __half* hin = (t & 1) ? hX : hY;
        __half* hout      = (t & 1) ? hY : hX;

        float g4[4][4];                              // [nt][gate], recurrent part
#pragma unroll
        for (int nt = 0; nt < 4; nt++)
#pragma unroll
            for (int g = 0; g < 4; g++) g4[nt][g] = 0.f;

        if (t > 0) {
            // per-warp poll: all 128 producer-warps of this group published h_{t-1}
            if (lane == 0) {
                while (ld_acq(flag) < 128u * (unsigned)t) { }
            }
            __syncwarp();

            // stage 8 chunks in 4 commit groups of 2
#pragma unroll
            for (int g2 = 0; g2 < 4; g2++) {
#pragma unroll
                for (int cc = 0; cc < 2; cc++) {
                    int c = g2 * 2 + cc;
                    cp_async16u(uH + (uint32_t)c * 4096 +
                                SWZ128((uint32_t)s_r * 128 + (uint32_t)s_q * 16),
                                hin + (size_t)(m0 + s_r) * Hn + c * 64 + s_q * 8);
                }
                cp_commit();
            }

            float acc[4][4];
#pragma unroll
            for (int nt = 0; nt < 4; nt++)
#pragma unroll
                for (int e = 0; e < 4; e++) acc[nt][e] = 0.f;

#pragma unroll
            for (int c = 0; c < 8; c++) {
                if (c == 0) { cp_wait3(); __syncthreads(); }
                else if (c == 2) { cp_wait2(); __syncthreads(); }
                else if (c == 4) { cp_wait1(); __syncthreads(); }
                else if (c == 6) { cp_wait0(); __syncthreads(); }
                const uint32_t uA = uH + (uint32_t)c * 4096;
                const uint32_t wh = uWhi + (uint32_t)c * 16384;
#pragma unroll
                for (int ks = 0; ks < 4; ks++) {
                    const uint32_t kbA = ((uint32_t)(32 * ks) + aKsel) ^ xorv;
                    const uint32_t kbB = ((uint32_t)(32 * ks) + bKsel) ^ xorv;
                    uint32_t a0[4], bh[8];
                    ldsm_x4(a0[0], a0[1], a0[2], a0[3], uA + aRow * 128 + kbA);
                    ldsm_x4(bh[0], bh[1], bh[2], bh[3], wh + bRow * 128 + kbB);
                    ldsm_x4(bh[4], bh[5], bh[6], bh[7], wh + (bRow + 16) * 128 + kbB);
#pragma unroll
                    for (int nt = 0; nt < 4; nt++)
                        mma_f16(acc[nt], a0, bh + nt * 2);
                }
            }

            // gate exchange: pair (tig, tig^1) swaps so each thread gets all
            // 4 gates of one (row, unit) per nt.
#pragma unroll
            for (int nt = 0; nt < 4; nt++) {
                float s0 = __shfl_xor_sync(0xffffffffu, oddt ? acc[nt][0] : acc[nt][2], 1);
                float s1 = __shfl_xor_sync(0xffffffffu, oddt ? acc[nt][1] : acc[nt][3], 1);
                g4[nt][0] = oddt ? s0 : acc[nt][0];
                g4[nt][1] = oddt ? s1 : acc[nt][1];
                g4[nt][2] = oddt ? acc[nt][2] : s0;
                g4[nt][3] = oddt ? acc[nt][3] : s1;
            }
        }

        // ---- cell update: 4 cells per thread ----
        float hn4[4];
#pragma unroll
        for (int nt = 0; nt < 4; nt++) {
            float gi = g4[nt][0] + xvf[nt][0];
            float gf = g4[nt][1] + xvf[nt][1];
            float gg = g4[nt][2] + xvf[nt][2];
            float go = g4[nt][3] + xvf[nt][3];
            float cn = fsig(gf) * creg[nt] + fsig(gi) * ftanh(gg);
            creg[nt] = cn;
            hn4[nt] = fsig(go) * ftanh(cn);
        }

        // write h (fp16) then per-warp release ASAP
#pragma unroll
        for (int nt = 0; nt < 4; nt++)
            hout[(size_t)crow * Hn + (ubase + nt * 2)] = __float2half(hn4[nt]);
        if (t < Tn - 1) {
            __syncwarp();
            if (lane == 0) red_rel_add(flag, 1u);
        }

        // off-critical-path: h_all / h_final, xg prefetch for t+1
        if (h_all) {
#pragma unroll
            for (int nt = 0; nt < 4; nt++)
                h_all[((size_t)crow * Tn + t) * Hn + (ubase + nt * 2)] = __float2half(hn4[nt]);
        }
        if (h_final && t == Tn - 1) {
#pragma unroll
            for (int nt = 0; nt < 4; nt++)
                h_final[(size_t)crow * Hn + (ubase + nt * 2)] = hn4[nt];
        }
        if (t < Tn - 1) {
            const __half* xr = xg + ((size_t)crow * Tn + (t + 1)) * G4H;
#pragma unroll
            for (int nt = 0; nt < 4; nt++) {
                uint2 p = __ldcg((const uint2*)(xr + (size_t)(ubase + nt * 2) * 4));
                float2 a = __half22float2(*(__half2*)&p.x);
                float2 b = __half22float2(*(__half2*)&p.y);
                xvf[nt][0] = a.x; xvf[nt][1] = a.y; xvf[nt][2] = b.x; xvf[nt][3] = b.y;
            }
        }
    }

    // ---- end of layer: full barrier once, then reset flags (replay-safe) ----
    group_barrier(grp);
    if (bu == 0 && tid == 0) *flag = 0u;
}

// ---------------- fp32 tiled GEMM (kept for FC1) ----------------------------
__global__ void __launch_bounds__(256, 2)
gemm_bias_kernel(const float* __restrict__ A,
                 const float* __restrict__ W,
                 const float* __restrict__ b1,
                 const float* __restrict__ b2,
                 float* __restrict__ C,
                 int M, int N, int K, int relu)
{
    __shared__ __align__(16) float As[2][128][GKC];
    __shared__ __align__(16) float Bs[2][GKC][64];
    const int m0 = blockIdx.y * 128;
    const int n0 = blockIdx.x * 64;
    const int tid = threadIdx.x;
    const int cx = tid & 15;
    const int ry = tid >> 4;

    ull acc01[8], acc23[8];
#pragma unroll
    for (int i = 0; i < 8; i++) { acc01[i] = 0ull; acc23[i] = 0ull; }

    const int nch = K / GKC;
    const int bcol = tid & 63, bq = tid >> 6;

#pragma unroll
    for (int i = 0; i < 2; i++) {
        int idx = tid + i * 256;
        cp_async16(&As[0][idx >> 2][(idx & 3) * 4],
                   A + (size_t)(m0 + (idx >> 2)) * K + (idx & 3) * 4);
    }
    cp_commit();
    float4 pW = *(const float4*)(W + (size_t)(n0 + bcol) * K + bq * 4);
    Bs[0][bq * 4 + 0][bcol] = pW.x;
    Bs[0][bq * 4 + 1][bcol] = pW.y;
    Bs[0][bq * 4 + 2][bcol] = pW.z;
    Bs[0][bq * 4 + 3][bcol] = pW.w;

    for (int c = 0; c < nch; c++) {
        cp_wait0();
        __syncthreads();
        const int buf = c & 1;
        const bool more = (c + 1 < nch);
        if (more) {
            int k0 = (c + 1) * GKC;
#pragma unroll
            for (int i = 0; i < 2; i++) {
                int idx = tid + i * 256;
                cp_async16(&As[buf ^ 1][idx >> 2][(idx & 3) * 4],
                           A + (size_t)(m0 + (idx >> 2)) * K + k0 + (idx & 3) * 4);
            }
            cp_commit();
            pW = *(const float4*)(W + (size_t)(n0 + bcol) * K + k0 + bq * 4);
        }
#pragma unroll
        for (int k4 = 0; k4 < GKC; k4 += 4) {
            float4 a4[8];
#pragma unroll
            for (int i = 0; i < 8; i++) a4[i] = *(const float4*)&As[buf][ry + 16 * i][k4];
#pragma unroll
            for (int j = 0; j < 4; j++) {
                float4 w4 = *(const float4*)&Bs[buf][k4 + j][4 * cx];
                ull w01 = *reinterpret_cast<ull*>(&w4.x);
                ull w23 = *reinterpret_cast<ull*>(&w4.z);
#pragma unroll
                for (int i = 0; i < 8; i++) {
                    float av = (j == 0) ? a4[i].x : (j == 1) ? a4[i].y : (j == 2) ? a4[i].z : a4[i].w;
                    ull ad = pack2dup(av);
                    ffma2(acc01[i], ad, w01);
                    ffma2(acc23[i], ad, w23);
                }
            }
        }
        if (more) {
            Bs[buf ^ 1][bq * 4 + 0][bcol] = pW.x;
            Bs[buf ^ 1][bq * 4 + 1][bcol] = pW.y;
            Bs[buf ^ 1][bq * 4 + 2][bcol] = pW.z;
            Bs[buf ^ 1][bq * 4 + 3][bcol] = pW.w;
        }
    }

    const int col = n0 + 4 * cx;
    float bb0 = b1[col + 0], bb1 = b1[col + 1], bb2 = b1[col + 2], bb3 = b1[col + 3];
    if (b2) { bb0 += b2[col + 0]; bb1 += b2[col + 1]; bb2 += b2[col + 2]; bb3 += b2[col + 3]; }
#pragma unroll
    for (int i = 0; i < 8; i++) {
        int row = m0 + ry + 16 * i;
        float2 p01 = unpack2(acc01[i]);
        float2 p23 = unpack2(acc23[i]);
        float4 v;
        v.x = p01.x + bb0; v.y = p01.y + bb1; v.z = p23.x + bb2; v.w = p23.y + bb3;
        if (relu) { v.x = fmaxf(v.x, 0.f); v.y = fmaxf(v.y, 0.f); v.z = fmaxf(v.z, 0.f); v.w = fmaxf(v.w, 0.f); }
        *(float4*)&C[(size_t)row * N + col] = v;
    }
}

// ---------------- FC2: out[256,8] = z @ W_fc2^T + b ------------------------
__global__ void fc2_kernel(const float* __restrict__ z,
                           const float* __restrict__ W,
                           const float* __restrict__ b,
                           float* __restrict__ out)
{
    int row = blockIdx.x;
    int o = threadIdx.y;
    int lane = threadIdx.x;
    float s = 0.f;
    const float* zr = z + (size_t)row * FCn;
    const float* wr = W + (size_t)o * FCn;
    for (int k = lane; k < FCn; k += 32) s += zr[k] * wr[k];
#pragma unroll
    for (int off = 16; off; off >>= 1) s += __shfl_down_sync(0xffffffffu, s, off);
    if (lane == 0) out[row * OUTn + o] = s + b[o];
}

// ---------------- host orchestration ---------------------------------------
extern "C" void kernel_launch(void* const* d_in, const int* in_sizes, int n_in,
                              void* d_out, int out_size)
{
    const float* x      = (const float*)d_in[0];
    const float* W_ih0  = (const float*)d_in[1];
    const float* W_hh0  = (const float*)d_in[2];
    const float* b_ih0  = (const float*)d_in[3];
    const float* b_hh0  = (const float*)d_in[4];
    const float* W_ih1  = (const float*)d_in[5];
    const float* W_hh1  = (const float*)d_in[6];
    const float* b_ih1  = (const float*)d_in[7];
    const float* b_hh1  = (const float*)d_in[8];
    const float* W_fc1  = (const float*)d_in[9];
    const float* b_fc1  = (const float*)d_in[10];
    const float* W_fc2  = (const float*)d_in[11];
    const float* b_fc2  = (const float*)d_in[12];
    float* out = (float*)d_out;

    float *hfin, *z;
    __half *xg, *h0h, *hX, *hY, *whhHi;
    uint4 *wb0h, *wb1h;
    cudaGetSymbolAddress((void**)&xg,    g_xg);
    cudaGetSymbolAddress((void**)&h0h,   g_h0h);
    cudaGetSymbolAddress((void**)&hfin,  g_hfin);
    cudaGetSymbolAddress((void**)&z,     g_z);
    cudaGetSymbolAddress((void**)&hX,    g_hX);
    cudaGetSymbolAddress((void**)&hY,    g_hY);
    cudaGetSymbolAddress((void**)&whhHi, g_Whh_hi);
    cudaGetSymbolAddress((void**)&wb0h,  g_Wb0hi);
    cudaGetSymbolAddress((void**)&wb1h,  g_Wb1hi);

    cudaFuncSetAttribute(mma_gemm_kernel, cudaFuncAttributeMaxDynamicSharedMemorySize, MMAG_SMEM);
    cudaFuncSetAttribute(lstm_layer_mma,  cudaFuncAttributeMaxDynamicSharedMemorySize, STEP_SMEM);

    const int MT = Bn * Tn;                 // 131072
    dim3 mmaGrid(G4H / 64, MT / 128);       // (32, 1024)
    dim3 stepGrid(16, MGRPS);               // (16, 8) = 128 blocks

    const size_t WHL = (size_t)G4H * Hn;    // per-layer whh elements
    prepack_whh<<<(G4H * Hn) / 256, 256>>>(W_hh0, whhHi);
    prepack_whh<<<(G4H * Hn) / 256, 256>>>(W_hh1, whhHi + WHL);
    prepack_b_kernel<<<(G4H * Dn) / 256, 256>>>(W_ih0, (__half*)wb0h, Dn);
    prepack_b_kernel<<<(G4H * Hn) / 256, 256>>>(W_ih1, (__half*)wb1h, Hn);

    // ---- Layer 0 ----  xg = x @ W_ih0^T + b_ih0 + b_hh0 (K=64, A fp32)
    mma_gemm_kernel<<<mmaGrid, 256, MMAG_SMEM>>>(x, wb0h, b_ih0, b_hh0, xg, Dn, G4H, 0);
    lstm_layer_mma<<<stepGrid, 256, STEP_SMEM>>>(xg, (const uint4*)whhHi,
                                                 hX, hY, h0h, (float*)0);

    // ---- Layer 1 ----  xg = h0 @ W_ih1^T + b_ih1 + b_hh1 (K=512, A fp16)
    mma_gemm_kernel<<<mmaGrid, 256, MMAG_SMEM>>>(h0h, wb1h, b_ih1, b_hh1, xg, Hn, G4H, 1);
    lstm_layer_mma<<<stepGrid, 256, STEP_SMEM>>>(xg, (const uint4*)(whhHi + WHL),
                                                 hX, hY, (__half*)0, hfin);

    // ---- FC head ----
    dim3 fc1Grid(FCn / 64, Bn / 128);       // (8, 2)
    gemm_bias_kernel<<<fc1Grid, 256>>>(hfin, W_fc1, b_fc1, (const float*)0, z, Bn, FCn, Hn, 1);
    fc2_kernel<<<Bn, dim3(32, 8)>>>(z, W_fc2, b_fc2, out);
}

// round 17
// speedup vs baseline: 1.2947x; 1.1670x over previous
#include <cuda_runtime.h>
#include <cuda_fp16.h>
#include <cstddef>
#include <cstdint>

// Problem constants
#define Bn   256
#define Tn   512
#define Dn   64
#define Hn   512
#define G4H  2048   // 4*H
#define FCn  512
#define OUTn 8

#define GKC   16          // k-chunk in fp32 gemm kernel
#define MGRPS 8           // m-groups (Bn/32)
#define GRP_BLOCKS 16     // blocks per m-group (2048 cols / 128)

typedef unsigned long long ull;

#define SWZ128(off) ((off) ^ (((off) >> 3) & 0x70))

// ---------------- scratch (device globals; no runtime allocation) ----------
// xg in fp16, gate-interleaved layout: xg[m, t, u*4 + g]
__device__ __half g_xg[(size_t)Bn * Tn * G4H];
__device__ __half g_h0h[(size_t)Bn * Tn * Hn];     // layer-0 h, fp16 (feeds layer-1 GEMM)
__device__ float g_hfin[Bn * Hn];
__device__ float g_z[Bn * FCn];
// fp16 h state double buffers
__device__ __half g_hX[Bn * Hn], g_hY[Bn * Hn];
// prepacked recurrent weights, fp16, [layer][u_tile(16)][chunk(8)][128n x 64k swizzled]
// n within tile = unit_local*4 + gate  (gate-interleaved)
__device__ __half g_Whh_hi[2][(size_t)G4H * Hn];
// fp16 pre-swizzled W_ih for mma gemm (gate-interleaved n)
__device__ uint4 g_Wb0hi[G4H * Dn / 8];            // layer0: 2048x64
__device__ uint4 g_Wb1hi[G4H * Hn / 8];            // layer1: 2048x512

// producer-progress flags (one per m-group, padded to 128B)
__device__ unsigned g_hflag[MGRPS * 32];

// ---------------- f32x2 packed helpers (fp32 FC1 gemm) ----------------------
__device__ __forceinline__ void ffma2(ull& d, ull a, ull b) {
    asm("fma.rn.f32x2 %0, %1, %2, %0;" : "+l"(d) : "l"(a), "l"(b));
}
__device__ __forceinline__ ull pack2dup(float x) {
    ull r; asm("mov.b64 %0, {%1, %1};" : "=l"(r) : "f"(x)); return r;
}
__device__ __forceinline__ float2 unpack2(ull v) {
    float2 f; asm("mov.b64 {%0, %1}, %2;" : "=f"(f.x), "=f"(f.y) : "l"(v)); return f;
}

// ---------------- fast activations (MUFU tanh; validated rel_err-neutral) ---
__device__ __forceinline__ float tanha(float x) {
    float r; asm("tanh.approx.f32 %0, %1;" : "=f"(r) : "f"(x)); return r;
}
__device__ __forceinline__ float fsig(float x) {
    return fmaf(0.5f, tanha(0.5f * x), 0.5f);
}
__device__ __forceinline__ float ftanh(float x) { return tanha(x); }

// ---------------- cp.async helpers -----------------------------------------
__device__ __forceinline__ void cp_async16(void* smem_dst, const void* gmem_src) {
    unsigned saddr = (unsigned)__cvta_generic_to_shared(smem_dst);
    asm volatile("cp.async.cg.shared.global [%0], [%1], 16;" :: "r"(saddr), "l"(gmem_src));
}
__device__ __forceinline__ void cp_async16u(unsigned saddr, const void* gmem_src) {
    asm volatile("cp.async.cg.shared.global [%0], [%1], 16;" :: "r"(saddr), "l"(gmem_src));
}
__device__ __forceinline__ void cp_commit() { asm volatile("cp.async.commit_group;"); }
__device__ __forceinline__ void cp_wait0()  { asm volatile("cp.async.wait_group 0;" ::: "memory"); }
__device__ __forceinline__ void cp_wait1()  { asm volatile("cp.async.wait_group 1;" ::: "memory"); }
__device__ __forceinline__ void cp_wait2()  { asm volatile("cp.async.wait_group 2;" ::: "memory"); }
__device__ __forceinline__ void cp_wait3()  { asm volatile("cp.async.wait_group 3;" ::: "memory"); }

__device__ __forceinline__ unsigned smem_u32(const void* p) {
    return (unsigned)__cvta_generic_to_shared(p);
}
__device__ __forceinline__ uint32_t cvt_f16x2(float hi, float lo) {
    uint32_t r; asm("cvt.rn.f16x2.f32 %0, %1, %2;" : "=r"(r) : "f"(hi), "f"(lo)); return r;
}

// ---------------- release/acquire flag helpers ------------------------------
__device__ __forceinline__ unsigned ld_acq(const unsigned* p) {
    unsigned v;
    asm volatile("ld.acquire.gpu.global.u32 %0, [%1];" : "=r"(v) : "l"(p));
    return v;
}
__device__ __forceinline__ void red_rel_add(unsigned* p, unsigned v) {
    asm volatile("red.release.gpu.global.add.u32 [%0], %1;" :: "l"(p), "r"(v));
}

// ---------------- warp-level mma helpers ------------------------------------
__device__ __forceinline__ void ldsm_x4(uint32_t& r0, uint32_t& r1, uint32_t& r2, uint32_t& r3,
                                        uint32_t addr) {
    asm volatile("ldmatrix.sync.aligned.m8n8.x4.shared.b16 {%0,%1,%2,%3}, [%4];"
                 : "=r"(r0), "=r"(r1), "=r"(r2), "=r"(r3) : "r"(addr));
}
__device__ __forceinline__ void mma_f16(float* d, const uint32_t* a, const uint32_t* b) {
    asm volatile("mma.sync.aligned.m16n8k16.row.col.f32.f16.f16.f32 "
                 "{%0,%1,%2,%3}, {%4,%5,%6,%7}, {%8,%9}, {%0,%1,%2,%3};"
                 : "+f"(d[0]), "+f"(d[1]), "+f"(d[2]), "+f"(d[3])
                 : "r"(a[0]), "r"(a[1]), "r"(a[2]), "r"(a[3]), "r"(b[0]), "r"(b[1]));
}

// ---------------- legacy full group barrier (used once per layer, at end) ---
struct __align__(128) BarSlot { unsigned count; unsigned gen; unsigned pad[30]; };
__device__ BarSlot g_bar[MGRPS];

__device__ __forceinline__ void group_barrier(int grp) {
    __syncthreads();
    __threadfence();
    if (threadIdx.x == 0) {
        unsigned gen = atomicAdd(&g_bar[grp].gen, 0u);
        unsigned arrived = atomicAdd(&g_bar[grp].count, 1u);
        if (arrived == GRP_BLOCKS - 1u) {
            atomicExch(&g_bar[grp].count, 0u);
            __threadfence();
            atomicExch(&g_bar[grp].gen, gen + 1u);
        } else {
            while (atomicAdd(&g_bar[grp].gen, 0u) == gen) { __nanosleep(20); }
        }
    }
    __syncthreads();
}

// ---------------- weight pre-pack kernels -----------------------------------
// Whh [4H, H] -> per u-tile (32 units x 4 gates = 128 n-cols, n = un*4+gate)
// x 8 k-chunks, each chunk a 128n x 64k fp16 tile, SW128 swizzled.
__global__ void prepack_whh(const float* __restrict__ Whh,
                            __half* __restrict__ hi)
{
    int i = blockIdx.x * blockDim.x + threadIdx.x;   // 0 .. 2048*512-1
    int k = i & 511;
    int row = i >> 9;                                 // gate*512 + unit_global
    int gate = row >> 9;
    int ug = row & 511;
    int bu = ug >> 5, un = ug & 31;
    int n = un * 4 + gate;                            // gate-interleaved
    int c = k >> 6, lk = k & 63;
    size_t off = ((size_t)(bu * 8 + c)) * 8192 + (SWZ128(n * 128 + lk * 2) >> 1);
    hi[off] = __float2half(Whh[(size_t)row * Hn + k]);
}

// W (2048 x K) -> fp16, per (ntile, kchunk) 64x64 tile, SW128.
// n' = u*4 + gate (gate-interleaved output columns).
__global__ void prepack_b_kernel(const float* __restrict__ W,
                                 __half* __restrict__ hi,
                                 int K)
{
    int i = blockIdx.x * blockDim.x + threadIdx.x;
    int k = i % K;
    int n_orig = i / K;                               // gate*512 + u
    int np = (n_orig & 511) * 4 + (n_orig >> 9);
    int ntile = np >> 6, ln = np & 63;
    int kc = k >> 6, lk = k & 63;
    int nch = K >> 6;
    size_t off = ((size_t)(ntile * nch + kc)) * 4096 + (SWZ128(ln * 128 + lk * 2) >> 1);
    hi[off] = __float2half(W[(size_t)n_orig * K + k]);
}

// inverse column permutation: n' -> orig row index in bias arrays
__device__ __forceinline__ int borig(int np) { return (np & 3) * 512 + (np >> 2); }

// ---------------- HMMA fp16 GEMM: C(half) = A @ W^T + b1 (+b2) -------------
// Double-buffered: stage(c+1) issued between the barrier and compute(c).
#define MMAG_SMEM (49152 + 1024)
__global__ void __launch_bounds__(256, 2)
mma_gemm_kernel(const void* __restrict__ Avoid,
                const uint4* __restrict__ Wbhi,
                const float* __restrict__ b1,
                const float* __restrict__ b2,
                __half* __restrict__ C,
                int K, int Ntot, int a_f16)
{
    extern __shared__ char dsm[];
    uint32_t usm = smem_u32(dsm);
    usm = (usm + 1023u) & ~1023u;
    const uint32_t uAbuf[2] = { usm,         usm + 16384 };   // 16KB each
    const uint32_t uBbuf[2] = { usm + 32768, usm + 40960 };   // 8KB each

    const int bn = blockIdx.x;
    const int m0 = blockIdx.y * 128;
    const int n0 = bn * 64;
    const int tid = threadIdx.x;
    const int w = tid >> 5;
    const int lane = tid & 31;
    const int mw = (w & 3) * 32;
    const int nw = (w >> 2) * 32;
    const int nch = K >> 6;

    const uint32_t xorv  = (uint32_t)(lane & 7) << 4;
    const uint32_t aRow  = mw + (lane & 15);
    const uint32_t aKsel = (uint32_t)(lane >> 4) << 4;
    const uint32_t bRow  = nw + (lane & 7) + ((lane >> 4) << 3);
    const uint32_t bKsel = (uint32_t)((lane >> 3) & 1) << 4;

    float acc[2][4][4];
#pragma unroll
    for (int mt = 0; mt < 2; mt++)
#pragma unroll
        for (int nt = 0; nt < 4; nt++)
#pragma unroll
            for (int e = 0; e < 4; e++) acc[mt][nt][e] = 0.f;

    auto stage = [&](int c, uint32_t uAd, uint32_t uBd) {
        const uint4* sbh = Wbhi + ((size_t)bn * nch + c) * 512;
        cp_async16u(uBd + (uint32_t)tid * 16,         sbh + tid);
        cp_async16u(uBd + (uint32_t)(tid + 256) * 16, sbh + tid + 256);
        if (a_f16) {
            const uint4* Af = (const uint4*)Avoid;
            const int krow = K >> 3;
#pragma unroll
            for (int j = 0; j < 4; j++) {
                int idx = tid + j * 256;
                int r = idx >> 3, q = idx & 7;
                cp_async16u(uAd + SWZ128((uint32_t)r * 128 + (uint32_t)q * 16),
                            Af + (size_t)(m0 + r) * krow + c * 8 + q);
            }
            cp_commit();
        } else {
            cp_commit();
            const float* A = (const float*)Avoid;
            const int k0 = c * 64;
#pragma unroll
            for (int it = 0; it < 8; it++) {
                int idx = tid + it * 256;
                int r = idx >> 4, f4 = idx & 15;
                float4 v = *(const float4*)(A + (size_t)(m0 + r) * K + k0 + f4 * 4);
                uint32_t h01 = cvt_f16x2(v.y, v.x);
                uint32_t h23 = cvt_f16x2(v.w, v.z);
                uint32_t sw = (uint32_t)r * 128 + (((uint32_t)f4 * 8) ^ (((uint32_t)r & 7) << 4));
                asm volatile("st.shared.v2.u32 [%0], {%1,%2};" :: "r"(uAd + sw), "r"(h01), "r"(h23));
            }
        }
    };

    stage(0, uAbuf[0], uBbuf[0]);

    for (int c = 0; c < nch; c++) {
        const int buf = c & 1;
        cp_wait0();
        __syncthreads();                 // chunk c staged; prior compute done
        if (c + 1 < nch) stage(c + 1, uAbuf[buf ^ 1], uBbuf[buf ^ 1]);

        const uint32_t uAhi = uAbuf[buf];
        const uint32_t uBhi = uBbuf[buf];
#pragma unroll
        for (int ks = 0; ks < 4; ks++) {
            const uint32_t kbA = ((uint32_t)(32 * ks) + aKsel) ^ xorv;
            const uint32_t kbB = ((uint32_t)(32 * ks) + bKsel) ^ xorv;
            uint32_t ah0[4], ah1[4];
            ldsm_x4(ah0[0], ah0[1], ah0[2], ah0[3], uAhi + aRow * 128 + kbA);
            ldsm_x4(ah1[0], ah1[1], ah1[2], ah1[3], uAhi + (aRow + 16) * 128 + kbA);
            uint32_t bh[8];
            ldsm_x4(bh[0], bh[1], bh[2], bh[3], uBhi + bRow * 128 + kbB);
            ldsm_x4(bh[4], bh[5], bh[6], bh[7], uBhi + (bRow + 16) * 128 + kbB);
#pragma unroll
            for (int mt = 0; mt < 2; mt++) {
                const uint32_t* Ah = mt ? ah1 : ah0;
#pragma unroll
                for (int nt = 0; nt < 4; nt++)
                    mma_f16(acc[mt][nt], Ah, bh + nt * 2);
            }
        }
    }

    const int gid = lane >> 2, tig = lane & 3;
    float2 bias[4];
#pragma unroll
    for (int nt = 0; nt < 4; nt++) {
        int col = n0 + nw + nt * 8 + tig * 2;
        int o0 = borig(col), o1 = borig(col + 1);
        bias[nt].x = b1[o0] + (b2 ? b2[o0] : 0.f);
        bias[nt].y = b1[o1] + (b2 ? b2[o1] : 0.f);
    }
#pragma unroll
    for (int mt = 0; mt < 2; mt++) {
        int row0 = m0 + mw + mt * 16 + gid;
#pragma unroll
        for (int nt = 0; nt < 4; nt++) {
            int col = n0 + nw + nt * 8 + tig * 2;
            uint32_t v0 = cvt_f16x2(acc[mt][nt][1] + bias[nt].y, acc[mt][nt][0] + bias[nt].x);
            uint32_t v1 = cvt_f16x2(acc[mt][nt][3] + bias[nt].y, acc[mt][nt][2] + bias[nt].x);
            *(uint32_t*)&C[(size_t)row0 * Ntot + col]       = v0;
            *(uint32_t*)&C[(size_t)(row0 + 8) * Ntot + col] = v1;
        }
    }
}

// ---------------- persistent HMMA fp16 LSTM layer kernel --------------------
// Grid (16, 8), 256 threads: block = 32 units x 4 gates (128 gate-interleaved
// n-cols) x 32 batch rows. W fp16 resident in smem (128KB). h fp16 staged per
// step (32KB, 4 commit groups of 2 chunks — first MMA starts after only 8KB).
// Sync: single per-group release flag; per-warp acquire poll.
// Epilogue: gate exchange via shfl.xor(1); h stores packed via shfl.xor(2)
// into one coalesced 8-byte store per thread.
#define STEP_SMEM (131072 + 32768 + 1024)
__global__ void __launch_bounds__(256)
lstm_layer_mma(const __half* __restrict__ xg,       // [B, T, 4H] gate-interleaved
               const uint4* __restrict__ Whi,       // prepacked, this layer
               __half* __restrict__ hX, __half* __restrict__ hY,
               __half* __restrict__ h_all,          // layer0: [B,T,H] fp16; else null
               float* __restrict__ h_final)         // layer1: [B,H]; else null
{
    extern __shared__ char dsm[];
    uint32_t usm = smem_u32(dsm);
    usm = (usm + 1023u) & ~1023u;
    const uint32_t uWhi = usm;                      // 8 chunks x 16KB = 128KB
    const uint32_t uH   = usm + 131072;             // 8 chunks x 4KB = 32KB

    const int bu  = blockIdx.x;                     // u-tile 0..15
    const int grp = blockIdx.y;                     // m-group 0..7
    const int m0  = grp * 32;
    const int tid = threadIdx.x;
    const int w   = tid >> 5;
    const int lane = tid & 31;
    const int mw = (w & 1) * 16;                    // 16 rows per warp (of 32)
    const int nw = (w >> 1) * 32;                   // 32 cols per warp (of 128)

    const uint32_t xorv  = (uint32_t)(lane & 7) << 4;
    const uint32_t aRow  = mw + (lane & 15);
    const uint32_t aKsel = (uint32_t)(lane >> 4) << 4;
    const uint32_t bRow  = nw + (lane & 7) + ((lane >> 4) << 3);
    const uint32_t bKsel = (uint32_t)((lane >> 3) & 1) << 4;
    const int gid = lane >> 2, tig = lane & 3;
    const bool oddt = (tig & 1);
    const int tigh = tig >> 1;

    unsigned* flag = &g_hflag[grp * 32];

    // ---- load resident weights (once): 128KB = 8192 uint4 ----
    {
        const uint4* sh = Whi + (size_t)bu * 8192;
#pragma unroll
        for (int j = 0; j < 32; j++) {
            int idx = tid + j * 256;
            cp_async16u(uWhi + (uint32_t)idx * 16, sh + idx);
        }
        cp_commit();
        cp_wait0();
        __syncthreads();
    }

    // ---- per-thread cell mapping (from MMA fragment + shfl exchange) ----
    const int crow   = m0 + mw + gid + 8 * (tig & 1);
    const int ubase  = bu * 32 + (w >> 1) * 8 + tigh;   // own units: ubase + 2*nt
    const int ustart = bu * 32 + (w >> 1) * 8 + 4 * tigh; // packed-store base (4 units)

    float creg[4] = {0.f, 0.f, 0.f, 0.f};
    float xvf[4][4];                                 // [nt][gate]
    {
        const __half* xr = xg + ((size_t)crow * Tn + 0) * G4H;
#pragma unroll
        for (int nt = 0; nt < 4; nt++) {
            uint2 p = __ldcg((const uint2*)(xr + (size_t)(ubase + nt * 2) * 4));
            float2 a = __half22float2(*(__half2*)&p.x);
            float2 b = __half22float2(*(__half2*)&p.y);
            xvf[nt][0] = a.x; xvf[nt][1] = a.y; xvf[nt][2] = b.x; xvf[nt][3] = b.y;
        }
    }

    // h staging per chunk: 32 rows x 64 k fp16 = 4KB = 256 cp.async = 1/thread
    const int s_r = tid >> 3, s_q = tid & 7;

    for (int t = 0; t < Tn; t++) {
        const __half* hin = (t & 1) ? hX : hY;
        __half* hout      = (t & 1) ? hY : hX;

        float g4[4][4];                              // [nt][gate], recurrent part
#pragma unroll
        for (int nt = 0; nt < 4; nt++)
#pragma unroll
            for (int g = 0; g < 4; g++) g4[nt][g] = 0.f;

        if (t > 0) {
            // per-warp poll: all 128 producer-warps of this group published h_{t-1}
            if (lane == 0) {
                while (ld_acq(flag) < 128u * (unsigned)t) { }
            }
            __syncwarp();

            // stage 8 chunks in 4 commit groups of 2
#pragma unroll
            for (int g2 = 0; g2 < 4; g2++) {
#pragma unroll
                for (int cc = 0; cc < 2; cc++) {
                    int c = g2 * 2 + cc;
                    cp_async16u(uH + (uint32_t)c * 4096 +
                                SWZ128((uint32_t)s_r * 128 + (uint32_t)s_q * 16),
                                hin + (size_t)(m0 + s_r) * Hn + c * 64 + s_q * 8);
                }
                cp_commit();
            }

            float acc[4][4];
#pragma unroll
            for (int nt = 0; nt < 4; nt++)
#pragma unroll
                for (int e = 0; e < 4; e++) acc[nt][e] = 0.f;

#pragma unroll
            for (int c = 0; c < 8; c++) {
                if (c == 0) { cp_wait3(); __syncthreads(); }
                else if (c == 2) { cp_wait2(); __syncthreads(); }
                else if (c == 4) { cp_wait1(); __syncthreads(); }
                else if (c == 6) { cp_wait0(); __syncthreads(); }
                const uint32_t uA = uH + (uint32_t)c * 4096;
                const uint32_t wh = uWhi + (uint32_t)c * 16384;
#pragma unroll
                for (int ks = 0; ks < 4; ks++) {
                    const uint32_t kbA = ((uint32_t)(32 * ks) + aKsel) ^ xorv;
                    const uint32_t kbB = ((uint32_t)(32 * ks) + bKsel) ^ xorv;
                    uint32_t a0[4], bh[8];
                    ldsm_x4(a0[0], a0[1], a0[2], a0[3], uA + aRow * 128 + kbA);
                    ldsm_x4(bh[0], bh[1], bh[2], bh[3], wh + bRow * 128 + kbB);
                    ldsm_x4(bh[4], bh[5], bh[6], bh[7], wh + (bRow + 16) * 128 + kbB);
#pragma unroll
                    for (int nt = 0; nt < 4; nt++)
                        mma_f16(acc[nt], a0, bh + nt * 2);
                }
            }

            // gate exchange: pair (tig, tig^1) swaps so each thread gets all
            // 4 gates of one (row, unit) per nt.
#pragma unroll
            for (int nt = 0; nt < 4; nt++) {
                float s0 = __shfl_xor_sync(0xffffffffu, oddt ? acc[nt][0] : acc[nt][2], 1);
                float s1 = __shfl_xor_sync(0xffffffffu, oddt ? acc[nt][1] : acc[nt][3], 1);
                g4[nt][0] = oddt ? s0 : acc[nt][0];
                g4[nt][1] = oddt ? s1 : acc[nt][1];
                g4[nt][2] = oddt ? acc[nt][2] : s0;
                g4[nt][3] = oddt ? acc[nt][3] : s1;
            }
        }

        // ---- cell update: 4 cells per thread ----
        float hn4[4];
#pragma unroll
        for (int nt = 0; nt < 4; nt++) {
            float gi = g4[nt][0] + xvf[nt][0];
            float gf = g4[nt][1] + xvf[nt][1];
            float gg = g4[nt][2] + xvf[nt][2];
            float go = g4[nt][3] + xvf[nt][3];
            float cn = fsig(gf) * creg[nt] + fsig(gi) * ftanh(gg);
            creg[nt] = cn;
            hn4[nt] = fsig(go) * ftanh(cn);
        }

        // ---- pack h with lane^2 partner (same row, units interleaved by 1)
        // tigh=0 thread ends with units ustart..ustart+3 = (own0, p0, own1, p1)
        // tigh=1 thread ends with units ustart..ustart+3 = (p2, own2, p3, own3)
        float sa = tigh ? hn4[0] : hn4[2];
        float sb = tigh ? hn4[1] : hn4[3];
        float ra = __shfl_xor_sync(0xffffffffu, sa, 2);
        float rb = __shfl_xor_sync(0xffffffffu, sb, 2);
        uint32_t p0 = tigh ? cvt_f16x2(hn4[2], ra) : cvt_f16x2(ra, hn4[0]);
        uint32_t p1 = tigh ? cvt_f16x2(hn4[3], rb) : cvt_f16x2(rb, hn4[1]);

        // single coalesced 8B store per thread, then release ASAP
        *(uint2*)(hout + (size_t)crow * Hn + ustart) = make_uint2(p0, p1);
        if (t < Tn - 1) {
            __syncwarp();
            if (lane == 0) red_rel_add(flag, 1u);
        }

        // off-critical-path: h_all / h_final (same packed values), xg prefetch
        if (h_all)
            *(uint2*)(h_all + ((size_t)crow * Tn + t) * Hn + ustart) = make_uint2(p0, p1);
        if (h_final && t == Tn - 1) {
            float4 vf = tigh ? make_float4(ra, hn4[2], rb, hn4[3])
                             : make_float4(hn4[0], ra, hn4[1], rb);
            *(float4*)&h_final[(size_t)crow * Hn + ustart] = vf;
        }
        if (t < Tn - 1) {
            const __half* xr = xg + ((size_t)crow * Tn + (t + 1)) * G4H;
#pragma unroll
            for (int nt = 0; nt < 4; nt++) {
                uint2 p = __ldcg((const uint2*)(xr + (size_t)(ubase + nt * 2) * 4));
                float2 a = __half22float2(*(__half2*)&p.x);
                float2 b = __half22float2(*(__half2*)&p.y);
                xvf[nt][0] = a.x; xvf[nt][1] = a.y; xvf[nt][2] = b.x; xvf[nt][3] = b.y;
            }
        }
    }

    // ---- end of layer: full barrier once, then reset flags (replay-safe) ----
    group_barrier(grp);
    if (bu == 0 && tid == 0) *flag = 0u;
}

// ---------------- fp32 tiled GEMM (kept for FC1) ----------------------------
__global__ void __launch_bounds__(256, 2)
gemm_bias_kernel(const float* __restrict__ A,
                 const float* __restrict__ W,
                 const float* __restrict__ b1,
                 const float* __restrict__ b2,
                 float* __restrict__ C,
                 int M, int N, int K, int relu)
{
    __shared__ __align__(16) float As[2][128][GKC];
    __shared__ __align__(16) float Bs[2][GKC][64];
    const int m0 = blockIdx.y * 128;
    const int n0 = blockIdx.x * 64;
    const int tid = threadIdx.x;
    const int cx = tid & 15;
    const int ry = tid >> 4;

    ull acc01[8], acc23[8];
#pragma unroll
    for (int i = 0; i < 8; i++) { acc01[i] = 0ull; acc23[i] = 0ull; }

    const int nch = K / GKC;
    const int bcol = tid & 63, bq = tid >> 6;

#pragma unroll
    for (int i = 0; i < 2; i++) {
        int idx = tid + i * 256;
        cp_async16(&As[0][idx >> 2][(idx & 3) * 4],
                   A + (size_t)(m0 + (idx >> 2)) * K + (idx & 3) * 4);
    }
    cp_commit();
    float4 pW = *(const float4*)(W + (size_t)(n0 + bcol) * K + bq * 4);
    Bs[0][bq * 4 + 0][bcol] = pW.x;
    Bs[0][bq * 4 + 1][bcol] = pW.y;
    Bs[0][bq * 4 + 2][bcol] = pW.z;
    Bs[0][bq * 4 + 3][bcol] = pW.w;

    for (int c = 0; c < nch; c++) {
        cp_wait0();
        __syncthreads();
        const int buf = c & 1;
        const bool more = (c + 1 < nch);
        if (more) {
            int k0 = (c + 1) * GKC;
#pragma unroll
            for (int i = 0; i < 2; i++) {
                int idx = tid + i * 256;
                cp_async16(&As[buf ^ 1][idx >> 2][(idx & 3) * 4],
                           A + (size_t)(m0 + (idx >> 2)) * K + k0 + (idx & 3) * 4);
            }
            cp_commit();
            pW = *(const float4*)(W + (size_t)(n0 + bcol) * K + k0 + bq * 4);
        }
#pragma unroll
        for (int k4 = 0; k4 < GKC; k4 += 4) {
            float4 a4[8];
#pragma unroll
            for (int i = 0; i < 8; i++) a4[i] = *(const float4*)&As[buf][ry + 16 * i][k4];
#pragma unroll
            for (int j = 0; j < 4; j++) {
                float4 w4 = *(const float4*)&Bs[buf][k4 + j][4 * cx];
                ull w01 = *reinterpret_cast<ull*>(&w4.x);
                ull w23 = *reinterpret_cast<ull*>(&w4.z);
#pragma unroll
                for (int i = 0; i < 8; i++) {
                    float av = (j == 0) ? a4[i].x : (j == 1) ? a4[i].y : (j == 2) ? a4[i].z : a4[i].w;
                    ull ad = pack2dup(av);
                    ffma2(acc01[i], ad, w01);
                    ffma2(acc23[i], ad, w23);
                }
            }
        }
        if (more) {
            Bs[buf ^ 1][bq * 4 + 0][bcol] = pW.x;
            Bs[buf ^ 1][bq * 4 + 1][bcol] = pW.y;
            Bs[buf ^ 1][bq * 4 + 2][bcol] = pW.z;
            Bs[buf ^ 1][bq * 4 + 3][bcol] = pW.w;
        }
    }

    const int col = n0 + 4 * cx;
    float bb0 = b1[col + 0], bb1 = b1[col + 1], bb2 = b1[col + 2], bb3 = b1[col + 3];
    if (b2) { bb0 += b2[col + 0]; bb1 += b2[col + 1]; bb2 += b2[col + 2]; bb3 += b2[col + 3]; }
#pragma unroll
    for (int i = 0; i < 8; i++) {
        int row = m0 + ry + 16 * i;
        float2 p01 = unpack2(acc01[i]);
        float2 p23 = unpack2(acc23[i]);
        float4 v;
        v.x = p01.x + bb0; v.y = p01.y + bb1; v.z = p23.x + bb2; v.w = p23.y + bb3;
        if (relu) { v.x = fmaxf(v.x, 0.f); v.y = fmaxf(v.y, 0.f); v.z = fmaxf(v.z, 0.f); v.w = fmaxf(v.w, 0.f); }
        *(float4*)&C[(size_t)row * N + col] = v;
    }
}

// ---------------- FC2: out[256,8] = z @ W_fc2^T + b ------------------------
__global__ void fc2_kernel(const float* __restrict__ z,
                           const float* __restrict__ W,
                           const float* __restrict__ b,
                           float* __restrict__ out)
{
    int row = blockIdx.x;
    int o = threadIdx.y;
    int lane = threadIdx.x;
    float s = 0.f;
    const float* zr = z + (size_t)row * FCn;
    const float* wr = W + (size_t)o * FCn;
    for (int k = lane; k < FCn; k += 32) s += zr[k] * wr[k];
#pragma unroll
    for (int off = 16; off; off >>= 1) s += __shfl_down_sync(0xffffffffu, s, off);
    if (lane == 0) out[row * OUTn + o] = s + b[o];
}

// ---------------- host orchestration ---------------------------------------
extern "C" void kernel_launch(void* const* d_in, const int* in_sizes, int n_in,
                              void* d_out, int out_size)
{
    const float* x      = (const float*)d_in[0];
    const float* W_ih0  = (const float*)d_in[1];
    const float* W_hh0  = (const float*)d_in[2];
    const float* b_ih0  = (const float*)d_in[3];
    const float* b_hh0  = (const float*)d_in[4];
    const float* W_ih1  = (const float*)d_in[5];
    const float* W_hh1  = (const float*)d_in[6];
    const float* b_ih1  = (const float*)d_in[7];
    const float* b_hh1  = (const float*)d_in[8];
    const float* W_fc1  = (const float*)d_in[9];
    const float* b_fc1  = (const float*)d_in[10];
    const float* W_fc2  = (const float*)d_in[11];
    const float* b_fc2  = (const float*)d_in[12];
    float* out = (float*)d_out;

    float *hfin, *z;
    __half *xg, *h0h, *hX, *hY, *whhHi;
    uint4 *wb0h, *wb1h;
    cudaGetSymbolAddress((void**)&xg,    g_xg);
    cudaGetSymbolAddress((void**)&h0h,   g_h0h);
    cudaGetSymbolAddress((void**)&hfin,  g_hfin);
    cudaGetSymbolAddress((void**)&z,     g_z);
    cudaGetSymbolAddress((void**)&hX,    g_hX);
    cudaGetSymbolAddress((void**)&hY,    g_hY);
    cudaGetSymbolAddress((void**)&whhHi, g_Whh_hi);
    cudaGetSymbolAddress((void**)&wb0h,  g_Wb0hi);
    cudaGetSymbolAddress((void**)&wb1h,  g_Wb1hi);

    cudaFuncSetAttribute(mma_gemm_kernel, cudaFuncAttributeMaxDynamicSharedMemorySize, MMAG_SMEM);
    cudaFuncSetAttribute(lstm_layer_mma,  cudaFuncAttributeMaxDynamicSharedMemorySize, STEP_SMEM);

    const int MT = Bn * Tn;                 // 131072
    dim3 mmaGrid(G4H / 64, MT / 128);       // (32, 1024)
    dim3 stepGrid(16, MGRPS);               // (16, 8) = 128 blocks

    const size_t WHL = (size_t)G4H * Hn;    // per-layer whh elements
    prepack_whh<<<(G4H * Hn) / 256, 256>>>(W_hh0, whhHi);
    prepack_whh<<<(G4H * Hn) / 256, 256>>>(W_hh1, whhHi + WHL);
    prepack_b_kernel<<<(G4H * Dn) / 256, 256>>>(W_ih0, (__half*)wb0h, Dn);
    prepack_b_kernel<<<(G4H * Hn) / 256, 256>>>(W_ih1, (__half*)wb1h, Hn);

    // ---- Layer 0 ----  xg = x @ W_ih0^T + b_ih0 + b_hh0 (K=64, A fp32)
    mma_gemm_kernel<<<mmaGrid, 256, MMAG_SMEM>>>(x, wb0h, b_ih0, b_hh0, xg, Dn, G4H, 0);
    lstm_layer_mma<<<stepGrid, 256, STEP_SMEM>>>(xg, (const uint4*)whhHi,
                                                 hX, hY, h0h, (float*)0);

    // ---- Layer 1 ----  xg = h0 @ W_ih1^T + b_ih1 + b_hh1 (K=512, A fp16)
    mma_gemm_kernel<<<mmaGrid, 256, MMAG_SMEM>>>(h0h, wb1h, b_ih1, b_hh1, xg, Hn, G4H, 1);
    lstm_layer_mma<<<stepGrid, 256, STEP_SMEM>>>(xg, (const uint4*)(whhHi + WHL),
                                                 hX, hY, (__half*)0, hfin);

    // ---- FC head ----
    dim3 fc1Grid(FCn / 64, Bn / 128);       // (8, 2)
    gemm_bias_kernel<<<fc1Grid, 256>>>(hfin, W_fc1, b_fc1, (const float*)0, z, Bn, FCn, Hn, 1);
    fc2_kernel<<<Bn, dim3(32, 8)>>>(z, W_fc2, b_fc2, out);
}